// round 1
// baseline (speedup 1.0000x reference)
#include <cuda_runtime.h>
#include <math.h>

#define Vv 20000
#define Lh 128
#define Dd 256
#define DEMOd 70
#define HIDd 1024
#define Nn 2048
#define KC 32
#define SST 132   // smem tile row stride (pad to dodge conflicts)

// ---- device scratch (static; no allocation) ----
__device__ float g_M[Dd * Dd];          // Wq @ Wk^T / sqrt(D)
__device__ float g_EM[Vv * Dd];         // E @ M
__device__ float g_ebar[Nn * Dd];       // pooled embedding  (sum_j p_j emb_j)
__device__ float g_R[Nn * Dd];          // ebar @ Wv  (= repr)
__device__ float g_H[Nn * HIDd];        // relu(X @ W1 + b1)
__device__ float g_loss[Nn];            // per-sample loss

// ---- 8x8 register-tile micro kernel over a KC x 128 smem panel pair ----
__device__ __forceinline__ void mm8x8(const float* As, const float* Bs,
                                      int i0, int j0, float acc[8][8]) {
#pragma unroll
    for (int k = 0; k < KC; k++) {
        const float* ar = As + k * SST + i0;
        const float* br = Bs + k * SST + j0;
        float4 a0 = *(const float4*)ar;
        float4 a1 = *(const float4*)(ar + 4);
        float4 b0 = *(const float4*)br;
        float4 b1 = *(const float4*)(br + 4);
        float av[8] = {a0.x, a0.y, a0.z, a0.w, a1.x, a1.y, a1.z, a1.w};
        float bv[8] = {b0.x, b0.y, b0.z, b0.w, b1.x, b1.y, b1.z, b1.w};
#pragma unroll
        for (int a = 0; a < 8; a++)
#pragma unroll
            for (int b = 0; b < 8; b++)
                acc[a][b] = fmaf(av[a], bv[b], acc[a][b]);
    }
}

// ---- K0: M = Wq @ Wk^T / sqrt(D).  grid (2,2), 256 thr ----
__global__ __launch_bounds__(256) void k0_M(const float* __restrict__ Wq,
                                            const float* __restrict__ Wk) {
    __shared__ float As[KC * SST], Bs[KC * SST];
    int r0 = blockIdx.x * 128, c0 = blockIdx.y * 128;
    int tid = threadIdx.x;
    int ty = tid >> 4, tx = tid & 15;
    int i0 = ty * 8, j0 = tx * 8;
    float acc[8][8] = {};
    for (int k0 = 0; k0 < Dd; k0 += KC) {
        __syncthreads();
#pragma unroll
        for (int r = 0; r < 16; r++) {
            int idx = tid + r * 256;
            int i = idx >> 5, k = idx & 31;
            As[k * SST + i] = Wq[(r0 + i) * Dd + k0 + k];
            Bs[k * SST + i] = Wk[(c0 + i) * Dd + k0 + k];
        }
        __syncthreads();
        mm8x8(As, Bs, i0, j0, acc);
    }
    const float sc = 1.0f / 16.0f;   // 1/sqrt(256)
#pragma unroll
    for (int a = 0; a < 8; a++)
#pragma unroll
        for (int b = 0; b < 8; b++)
            g_M[(r0 + i0 + a) * Dd + c0 + j0 + b] = acc[a][b] * sc;
}

// ---- K1: EM = E @ M.  grid (157,2), 256 thr ----
__global__ __launch_bounds__(256) void k1_EM(const float* __restrict__ E) {
    __shared__ float As[KC * SST], Bs[KC * SST];
    int r0 = blockIdx.x * 128, c0 = blockIdx.y * 128;
    int tid = threadIdx.x;
    int ty = tid >> 4, tx = tid & 15;
    int i0 = ty * 8, j0 = tx * 8;
    float acc[8][8] = {};
    for (int k0 = 0; k0 < Dd; k0 += KC) {
        __syncthreads();
#pragma unroll
        for (int r = 0; r < 16; r++) {
            int idx = tid + r * 256;
            int iA = idx >> 5, kA = idx & 31;
            int rowA = r0 + iA;
            As[kA * SST + iA] = (rowA < Vv) ? E[rowA * Dd + k0 + kA] : 0.0f;
            int kB = idx >> 7, jB = idx & 127;
            Bs[kB * SST + jB] = g_M[(k0 + kB) * Dd + c0 + jB];
        }
        __syncthreads();
        mm8x8(As, Bs, i0, j0, acc);
    }
#pragma unroll
    for (int a = 0; a < 8; a++) {
        int row = r0 + i0 + a;
        if (row < Vv)
#pragma unroll
            for (int b = 0; b < 8; b++)
                g_EM[row * Dd + c0 + j0 + b] = acc[a][b];
    }
}

// ---- K2: per-sample fused attention + pooling -> g_ebar.  grid 2048, 256 thr ----
__global__ __launch_bounds__(256, 2) void k2_attn(
    const float* __restrict__ E, const int* __restrict__ codes,
    const float* __restrict__ ht, const float* __restrict__ et,
    const int* __restrict__ lengths, const float* __restrict__ c_attn,
    const float* __restrict__ c_pool) {
    extern __shared__ float sm[];
    float* S  = sm;                         // 128*128
    float* As = sm + Lh * Lh;               // KC*SST  (t rows = EM gather)
    float* Bs = As + KC * SST;              // KC*SST  (emb rows = E gather)
    float* wv = Bs + KC * SST;              // 128 pooling weights
    float* pv = wv + Lh;                    // 128 column weights p_j
    float* tv = pv + Lh;                    // 128 hist times
    int*   cd = (int*)(tv + Lh);            // 128 codes

    int n = blockIdx.x;
    int tid = threadIdx.x;
    int len = lengths[n];

    if (tid < Lh) {
        cd[tid] = codes[n * Lh + tid];
        tv[tid] = ht[n * Lh + tid];
    }
    __syncthreads();

    // pooling weights w_i = softmax_i(-c_pool*(event_time - t_i)), valid i only
    if (tid < 32) {
        float cp = c_pool[0];
        float e_t = et[n];
        float m = -1e30f;
        for (int i = tid; i < len; i += 32) m = fmaxf(m, -cp * (e_t - tv[i]));
#pragma unroll
        for (int o = 16; o; o >>= 1) m = fmaxf(m, __shfl_xor_sync(0xffffffffu, m, o));
        float ssum = 0.f;
        for (int i = tid; i < len; i += 32) {
            float e = __expf(-cp * (e_t - tv[i]) - m);
            wv[i] = e;
            ssum += e;
        }
#pragma unroll
        for (int o = 16; o; o >>= 1) ssum += __shfl_xor_sync(0xffffffffu, ssum, o);
        float inv = 1.0f / ssum;
        for (int i = tid; i < len; i += 32) wv[i] *= inv;
    }

    int ty = tid >> 4, tx = tid & 15;
    int i0 = ty * 8, j0 = tx * 8;
    bool active = (i0 < len) && (j0 < len);
    float acc[8][8] = {};

    for (int k0 = 0; k0 < Dd; k0 += KC) {
        __syncthreads();
#pragma unroll
        for (int r = 0; r < 16; r++) {
            int idx = tid + r * 256;
            int i = idx >> 5, k = idx & 31;
            int c = cd[i];
            As[k * SST + i] = g_EM[c * Dd + k0 + k];
            Bs[k * SST + i] = E[c * Dd + k0 + k];
        }
        __syncthreads();
        if (active) mm8x8(As, Bs, i0, j0, acc);
    }
    __syncthreads();

    float ca = c_attn[0];
    if (active) {
#pragma unroll
        for (int a = 0; a < 8; a++) {
            float ti = tv[i0 + a];
#pragma unroll
            for (int b = 0; b < 8; b++)
                S[(i0 + a) * Lh + j0 + b] = acc[a][b] - ca * fabsf(ti - tv[j0 + b]);
        }
    }
    __syncthreads();

    // row softmax (valid j) scaled by w_i, stored in place
    int warp = tid >> 5, lane = tid & 31;
    for (int i = warp; i < len; i += 8) {
        float* row = S + i * Lh;
        float m = -1e30f;
        for (int j = lane; j < len; j += 32) m = fmaxf(m, row[j]);
#pragma unroll
        for (int o = 16; o; o >>= 1) m = fmaxf(m, __shfl_xor_sync(0xffffffffu, m, o));
        float ssum = 0.f;
        for (int j = lane; j < len; j += 32) {
            float e = __expf(row[j] - m);
            row[j] = e;
            ssum += e;
        }
#pragma unroll
        for (int o = 16; o; o >>= 1) ssum += __shfl_xor_sync(0xffffffffu, ssum, o);
        float sc = wv[i] / ssum;
        for (int j = lane; j < len; j += 32) row[j] *= sc;
    }
    __syncthreads();

    // p_j = sum_i w_i * a_ij
    if (tid < Lh && tid < len) {
        float p = 0.f;
        for (int i = 0; i < len; i++) p += S[i * Lh + tid];
        pv[tid] = p;
    }
    __syncthreads();

    // ebar_d = sum_j p_j * emb_j[d]
    float a = 0.f;
    for (int j = 0; j < len; j++) a = fmaf(pv[j], E[cd[j] * Dd + tid], a);
    g_ebar[n * Dd + tid] = a;
}

// ---- K3a: R = ebar @ Wv.  grid (16,2), 256 thr ----
__global__ __launch_bounds__(256) void k3a_R(const float* __restrict__ Wv) {
    __shared__ float As[KC * SST], Bs[KC * SST];
    int r0 = blockIdx.x * 128, c0 = blockIdx.y * 128;
    int tid = threadIdx.x;
    int ty = tid >> 4, tx = tid & 15;
    int i0 = ty * 8, j0 = tx * 8;
    float acc[8][8] = {};
    for (int k0 = 0; k0 < Dd; k0 += KC) {
        __syncthreads();
#pragma unroll
        for (int r = 0; r < 16; r++) {
            int idx = tid + r * 256;
            int iA = idx >> 5, kA = idx & 31;
            As[kA * SST + iA] = g_ebar[(r0 + iA) * Dd + k0 + kA];
            int kB = idx >> 7, jB = idx & 127;
            Bs[kB * SST + jB] = Wv[(k0 + kB) * Dd + c0 + jB];
        }
        __syncthreads();
        mm8x8(As, Bs, i0, j0, acc);
    }
#pragma unroll
    for (int a = 0; a < 8; a++)
#pragma unroll
        for (int b = 0; b < 8; b++)
            g_R[(r0 + i0 + a) * Dd + c0 + j0 + b] = acc[a][b];
}

// ---- K3b: H = relu([demo, R] @ W1 + b1).  grid (16,8), 256 thr, K=326 ----
__global__ __launch_bounds__(256) void k3b_H(const float* __restrict__ demo,
                                             const float* __restrict__ W1,
                                             const float* __restrict__ b1) {
    __shared__ float As[KC * SST], Bs[KC * SST];
    int r0 = blockIdx.x * 128, c0 = blockIdx.y * 128;
    int tid = threadIdx.x;
    int ty = tid >> 4, tx = tid & 15;
    int i0 = ty * 8, j0 = tx * 8;
    const int Ktot = DEMOd + Dd;   // 326
    float acc[8][8] = {};
    for (int k0 = 0; k0 < 352; k0 += KC) {
        __syncthreads();
#pragma unroll
        for (int r = 0; r < 16; r++) {
            int idx = tid + r * 256;
            int iA = idx >> 5, kA = idx & 31;
            int kk = k0 + kA;
            float va = 0.f;
            if (kk < Ktot)
                va = (kk < DEMOd) ? demo[(r0 + iA) * DEMOd + kk]
                                  : g_R[(r0 + iA) * Dd + (kk - DEMOd)];
            As[kA * SST + iA] = va;
            int kB = idx >> 7, jB = idx & 127;
            int kk2 = k0 + kB;
            Bs[kB * SST + jB] = (kk2 < Ktot) ? W1[kk2 * HIDd + c0 + jB] : 0.f;
        }
        __syncthreads();
        mm8x8(As, Bs, i0, j0, acc);
    }
#pragma unroll
    for (int a = 0; a < 8; a++)
#pragma unroll
        for (int b = 0; b < 8; b++) {
            float h = acc[a][b] + b1[c0 + j0 + b];
            g_H[(r0 + i0 + a) * HIDd + c0 + j0 + b] = fmaxf(h, 0.f);
        }
}

// ---- K3c: per-sample logit + BCE-with-logits (pos_weight=2).  grid 256, 256 thr ----
__global__ __launch_bounds__(256) void k3c_loss(const float* __restrict__ W2,
                                                const float* __restrict__ b2,
                                                const float* __restrict__ labels) {
    int warp = threadIdx.x >> 5, lane = threadIdx.x & 31;
    int n = blockIdx.x * 8 + warp;
    float s = 0.f;
    for (int q = lane; q < HIDd; q += 32) s = fmaf(g_H[n * HIDd + q], W2[q], s);
#pragma unroll
    for (int o = 16; o; o >>= 1) s += __shfl_xor_sync(0xffffffffu, s, o);
    if (lane == 0) {
        float logit = s + b2[0];
        float y = labels[n];
        // softplus(x) stable; softplus(-x) = softplus(x) - x
        float sp = (logit > 0.f) ? logit + log1pf(expf(-logit)) : log1pf(expf(logit));
        float sp_neg = sp - logit;
        g_loss[n] = 2.0f * y * sp_neg + (1.0f - y) * sp;
    }
}

// ---- K4: deterministic tree-reduce mean + reg.  grid 1, 256 thr ----
__global__ __launch_bounds__(256) void k4_final(const float* __restrict__ c_attn,
                                                const float* __restrict__ c_pool,
                                                float* __restrict__ out) {
    __shared__ float red[256];
    int tid = threadIdx.x;
    float s = 0.f;
    for (int i = tid; i < Nn; i += 256) s += g_loss[i];
    red[tid] = s;
    __syncthreads();
    for (int st = 128; st; st >>= 1) {
        if (tid < st) red[tid] += red[tid + st];
        __syncthreads();
    }
    if (tid == 0) {
        float ca = c_attn[0], cp = c_pool[0];
        out[0] = red[0] / (float)Nn + ca * ca + cp * cp;
    }
}

static const int K2_SMEM = (Lh * Lh + 2 * KC * SST + 3 * Lh + Lh) * 4;  // 101376 B

extern "C" void kernel_launch(void* const* d_in, const int* in_sizes, int n_in,
                              void* d_out, int out_size) {
    const float* E       = (const float*)d_in[0];
    const float* Wq      = (const float*)d_in[1];
    const float* Wk      = (const float*)d_in[2];
    const float* Wv      = (const float*)d_in[3];
    const float* c_attn  = (const float*)d_in[4];
    const float* c_pool  = (const float*)d_in[5];
    const float* W1      = (const float*)d_in[6];
    const float* b1      = (const float*)d_in[7];
    const float* W2      = (const float*)d_in[8];
    const float* b2      = (const float*)d_in[9];
    const float* demo    = (const float*)d_in[10];
    const float* ht      = (const float*)d_in[11];
    const float* et      = (const float*)d_in[12];
    const float* labels  = (const float*)d_in[13];
    const int*   codes   = (const int*)d_in[14];
    const int*   lengths = (const int*)d_in[15];
    float* out = (float*)d_out;

    cudaFuncSetAttribute(k2_attn, cudaFuncAttributeMaxDynamicSharedMemorySize, K2_SMEM);

    k0_M<<<dim3(2, 2), 256>>>(Wq, Wk);
    k1_EM<<<dim3(157, 2), 256>>>(E);
    k2_attn<<<Nn, 256, K2_SMEM>>>(E, codes, ht, et, lengths, c_attn, c_pool);
    k3a_R<<<dim3(16, 2), 256>>>(Wv);
    k3b_H<<<dim3(16, 8), 256>>>(demo, W1, b1);
    k3c_loss<<<Nn / 8, 256>>>(W2, b2, labels);
    k4_final<<<1, 256>>>(c_attn, c_pool, out);
}

// round 3
// speedup vs baseline: 1.2094x; 1.2094x over previous
#include <cuda_runtime.h>
#include <math.h>

#define Vv 20000
#define Lh 128
#define Dd 256
#define DEMOd 70
#define HIDd 1024
#define Nn 2048
#define KC 32
#define SST 132    // 128-wide smem panel stride
#define SST64 68   // 64-wide smem panel stride

typedef unsigned long long u64;

__device__ __forceinline__ u64 ffma2(u64 a, u64 b, u64 c) {
    u64 d; asm("fma.rn.f32x2 %0,%1,%2,%3;" : "=l"(d) : "l"(a), "l"(b), "l"(c)); return d;
}
__device__ __forceinline__ u64 splat2(float x) {
    u64 d; asm("mov.b64 %0,{%1,%1};" : "=l"(d) : "f"(x)); return d;
}
__device__ __forceinline__ u64 pk(float x, float y) {
    u64 d; asm("mov.b64 %0,{%1,%2};" : "=l"(d) : "f"(x), "f"(y)); return d;
}
__device__ __forceinline__ float2 unpk(u64 v) {
    float2 r; asm("mov.b64 {%0,%1},%2;" : "=f"(r.x), "=f"(r.y) : "l"(v)); return r;
}

// ---- device scratch ----
__device__ float g_M[Dd * Dd];
__device__ float g_EM[Vv * Dd];
__device__ float g_ebar[Nn * Dd];
__device__ float g_R[Nn * Dd];
__device__ float g_H[Nn * HIDd];
__device__ float g_loss[Nn];

// ---- packed 8x8 micro-kernel: acc[a][b] holds rows (i0+2a, i0+2a+1), col j0+b ----
__device__ __forceinline__ void mm8x8p(const float* As, const float* Bs,
                                       int i0, int j0, u64 acc[4][8]) {
#pragma unroll
    for (int k = 0; k < KC; k++) {
        const float* ar = As + k * SST + i0;
        const float* br = Bs + k * SST + j0;
        float4 a0 = *(const float4*)ar;
        float4 a1 = *(const float4*)(ar + 4);
        float4 b0 = *(const float4*)br;
        float4 b1 = *(const float4*)(br + 4);
        u64 av[4] = {pk(a0.x, a0.y), pk(a0.z, a0.w), pk(a1.x, a1.y), pk(a1.z, a1.w)};
        float bv[8] = {b0.x, b0.y, b0.z, b0.w, b1.x, b1.y, b1.z, b1.w};
#pragma unroll
        for (int b = 0; b < 8; b++) {
            u64 bs = splat2(bv[b]);
#pragma unroll
            for (int a = 0; a < 4; a++) acc[a][b] = ffma2(av[a], bs, acc[a][b]);
        }
    }
}

// ---- packed 4x4 micro-kernel for 64x64 tiles ----
__device__ __forceinline__ void mm4x4p(const float* As, const float* Bs,
                                       int i0, int j0, u64 acc[2][4]) {
#pragma unroll
    for (int k = 0; k < KC; k++) {
        float4 a0 = *(const float4*)(As + k * SST64 + i0);
        float4 b0 = *(const float4*)(Bs + k * SST64 + j0);
        u64 av[2] = {pk(a0.x, a0.y), pk(a0.z, a0.w)};
        float bv[4] = {b0.x, b0.y, b0.z, b0.w};
#pragma unroll
        for (int b = 0; b < 4; b++) {
            u64 bs = splat2(bv[b]);
#pragma unroll
            for (int a = 0; a < 2; a++) acc[a][b] = ffma2(av[a], bs, acc[a][b]);
        }
    }
}

// ---- K0: M = Wq @ Wk^T / 16.  64x64 tiles, grid (4,4), 256 thr ----
__global__ __launch_bounds__(256) void k0_M(const float* __restrict__ Wq,
                                            const float* __restrict__ Wk) {
    __shared__ float As[KC * SST64], Bs[KC * SST64];
    int r0 = blockIdx.x * 64, c0 = blockIdx.y * 64;
    int tid = threadIdx.x;
    int ty = tid >> 4, tx = tid & 15;
    int i0 = ty * 4, j0 = tx * 4;
    u64 acc[2][4];
#pragma unroll
    for (int a = 0; a < 2; a++)
#pragma unroll
        for (int b = 0; b < 4; b++) acc[a][b] = splat2(0.f);
    for (int k0 = 0; k0 < Dd; k0 += KC) {
        __syncthreads();
#pragma unroll
        for (int r = 0; r < 8; r++) {
            int idx = tid + r * 256;
            int i = idx >> 5, k = idx & 31;
            As[k * SST64 + i] = Wq[(r0 + i) * Dd + k0 + k];
            Bs[k * SST64 + i] = Wk[(c0 + i) * Dd + k0 + k];
        }
        __syncthreads();
        mm4x4p(As, Bs, i0, j0, acc);
    }
    const float sc = 1.0f / 16.0f;
#pragma unroll
    for (int a = 0; a < 2; a++)
#pragma unroll
        for (int b = 0; b < 4; b++) {
            float2 v = unpk(acc[a][b]);
            g_M[(r0 + i0 + 2 * a) * Dd + c0 + j0 + b] = v.x * sc;
            g_M[(r0 + i0 + 2 * a + 1) * Dd + c0 + j0 + b] = v.y * sc;
        }
}

// ---- K1: EM = E @ M.  128x128 tiles, grid (157,2), 256 thr ----
__global__ __launch_bounds__(256) void k1_EM(const float* __restrict__ E) {
    __shared__ float As[KC * SST], Bs[KC * SST];
    int r0 = blockIdx.x * 128, c0 = blockIdx.y * 128;
    int tid = threadIdx.x;
    int ty = tid >> 4, tx = tid & 15;
    int i0 = ty * 8, j0 = tx * 8;
    u64 acc[4][8];
#pragma unroll
    for (int a = 0; a < 4; a++)
#pragma unroll
        for (int b = 0; b < 8; b++) acc[a][b] = splat2(0.f);
    for (int k0 = 0; k0 < Dd; k0 += KC) {
        __syncthreads();
#pragma unroll
        for (int r = 0; r < 16; r++) {
            int idx = tid + r * 256;
            int iA = idx >> 5, kA = idx & 31;
            int rowA = r0 + iA;
            As[kA * SST + iA] = (rowA < Vv) ? E[rowA * Dd + k0 + kA] : 0.0f;
            int kB = idx >> 7, jB = idx & 127;
            Bs[kB * SST + jB] = g_M[(k0 + kB) * Dd + c0 + jB];
        }
        __syncthreads();
        mm8x8p(As, Bs, i0, j0, acc);
    }
#pragma unroll
    for (int a = 0; a < 4; a++) {
        int ra = r0 + i0 + 2 * a;
#pragma unroll
        for (int b = 0; b < 8; b++) {
            float2 v = unpk(acc[a][b]);
            if (ra < Vv) g_EM[ra * Dd + c0 + j0 + b] = v.x;
            if (ra + 1 < Vv) g_EM[(ra + 1) * Dd + c0 + j0 + b] = v.y;
        }
    }
}

// ---- K2: per-sample fused attention + pooling -> g_ebar.  grid 2048, 256 thr ----
__global__ __launch_bounds__(256, 2) void k2_attn(
    const float* __restrict__ E, const int* __restrict__ codes,
    const float* __restrict__ ht, const float* __restrict__ et,
    const int* __restrict__ lengths, const float* __restrict__ c_attn,
    const float* __restrict__ c_pool) {
    extern __shared__ float sm[];
    float* S  = sm;                 // 128*128
    float* As = sm + Lh * Lh;       // KC*SST
    float* Bs = As + KC * SST;      // KC*SST
    float* wv = Bs + KC * SST;      // 128
    float* pv = wv + Lh;            // 128
    float* tv = pv + Lh;            // 128
    int*   cd = (int*)(tv + Lh);    // 128

    int n = blockIdx.x;
    int tid = threadIdx.x;
    int len = lengths[n];

    if (tid < Lh) {
        cd[tid] = codes[n * Lh + tid];
        tv[tid] = ht[n * Lh + tid];
    }
    __syncthreads();

    if (tid < 32) {
        float cp = c_pool[0];
        float e_t = et[n];
        float m = -1e30f;
        for (int i = tid; i < len; i += 32) m = fmaxf(m, -cp * (e_t - tv[i]));
#pragma unroll
        for (int o = 16; o; o >>= 1) m = fmaxf(m, __shfl_xor_sync(0xffffffffu, m, o));
        float ssum = 0.f;
        for (int i = tid; i < len; i += 32) {
            float e = __expf(-cp * (e_t - tv[i]) - m);
            wv[i] = e;
            ssum += e;
        }
#pragma unroll
        for (int o = 16; o; o >>= 1) ssum += __shfl_xor_sync(0xffffffffu, ssum, o);
        float inv = 1.0f / ssum;
        for (int i = tid; i < len; i += 32) wv[i] *= inv;
    }

    int ty = tid >> 4, tx = tid & 15;
    int i0 = ty * 8, j0 = tx * 8;
    bool active = (i0 < len) && (j0 < len);
    u64 acc[4][8];
#pragma unroll
    for (int a = 0; a < 4; a++)
#pragma unroll
        for (int b = 0; b < 8; b++) acc[a][b] = splat2(0.f);

    for (int k0 = 0; k0 < Dd; k0 += KC) {
        __syncthreads();
#pragma unroll
        for (int r = 0; r < 16; r++) {
            int idx = tid + r * 256;
            int i = idx >> 5, k = idx & 31;
            int c = cd[i];
            As[k * SST + i] = g_EM[c * Dd + k0 + k];
            Bs[k * SST + i] = E[c * Dd + k0 + k];
        }
        __syncthreads();
        if (active) mm8x8p(As, Bs, i0, j0, acc);
    }
    __syncthreads();

    float ca = c_attn[0];
    if (active) {
#pragma unroll
        for (int a = 0; a < 4; a++) {
            int ia = i0 + 2 * a;
            float ti0 = tv[ia], ti1 = tv[ia + 1];
#pragma unroll
            for (int b = 0; b < 8; b++) {
                float2 v = unpk(acc[a][b]);
                int j = j0 + b;
                float tj = tv[j];
                S[ia * Lh + j] = v.x - ca * fabsf(ti0 - tj);
                S[(ia + 1) * Lh + j] = v.y - ca * fabsf(ti1 - tj);
            }
        }
    }
    __syncthreads();

    // row softmax scaled by w_i, in place
    int warp = tid >> 5, lane = tid & 31;
    for (int i = warp; i < len; i += 8) {
        float* row = S + i * Lh;
        float m = -1e30f;
        for (int j = lane; j < len; j += 32) m = fmaxf(m, row[j]);
#pragma unroll
        for (int o = 16; o; o >>= 1) m = fmaxf(m, __shfl_xor_sync(0xffffffffu, m, o));
        float ssum = 0.f;
        for (int j = lane; j < len; j += 32) {
            float e = __expf(row[j] - m);
            row[j] = e;
            ssum += e;
        }
#pragma unroll
        for (int o = 16; o; o >>= 1) ssum += __shfl_xor_sync(0xffffffffu, ssum, o);
        float sc = wv[i] / ssum;
        for (int j = lane; j < len; j += 32) row[j] *= sc;
    }
    __syncthreads();

    // p_j = sum_i w_i * a_ij
    if (tid < Lh && tid < len) {
        float p = 0.f;
        for (int i = 0; i < len; i++) p += S[i * Lh + tid];
        pv[tid] = p;
    }
    __syncthreads();

    // ebar_d = sum_j p_j * emb_j[d]
    float a = 0.f;
    for (int j = 0; j < len; j++) a = fmaf(pv[j], E[cd[j] * Dd + tid], a);
    g_ebar[n * Dd + tid] = a;
}

// ---- K3a: R = ebar @ Wv.  64x64 tiles, grid (32,4), 256 thr ----
__global__ __launch_bounds__(256) void k3a_R(const float* __restrict__ Wv) {
    __shared__ float As[KC * SST64], Bs[KC * SST64];
    int r0 = blockIdx.x * 64, c0 = blockIdx.y * 64;
    int tid = threadIdx.x;
    int ty = tid >> 4, tx = tid & 15;
    int i0 = ty * 4, j0 = tx * 4;
    u64 acc[2][4];
#pragma unroll
    for (int a = 0; a < 2; a++)
#pragma unroll
        for (int b = 0; b < 4; b++) acc[a][b] = splat2(0.f);
    for (int k0 = 0; k0 < Dd; k0 += KC) {
        __syncthreads();
#pragma unroll
        for (int r = 0; r < 8; r++) {
            int idx = tid + r * 256;
            int iA = idx >> 5, kA = idx & 31;
            As[kA * SST64 + iA] = g_ebar[(r0 + iA) * Dd + k0 + kA];
            int kB = idx >> 6, jB = idx & 63;
            Bs[kB * SST64 + jB] = Wv[(k0 + kB) * Dd + c0 + jB];
        }
        __syncthreads();
        mm4x4p(As, Bs, i0, j0, acc);
    }
#pragma unroll
    for (int a = 0; a < 2; a++)
#pragma unroll
        for (int b = 0; b < 4; b++) {
            float2 v = unpk(acc[a][b]);
            g_R[(r0 + i0 + 2 * a) * Dd + c0 + j0 + b] = v.x;
            g_R[(r0 + i0 + 2 * a + 1) * Dd + c0 + j0 + b] = v.y;
        }
}

// ---- K3b: H = relu([demo, R] @ W1 + b1).  64x64 tiles, grid (32,16), K=326->352 ----
__global__ __launch_bounds__(256) void k3b_H(const float* __restrict__ demo,
                                             const float* __restrict__ W1,
                                             const float* __restrict__ b1) {
    __shared__ float As[KC * SST64], Bs[KC * SST64];
    int r0 = blockIdx.x * 64, c0 = blockIdx.y * 64;
    int tid = threadIdx.x;
    int ty = tid >> 4, tx = tid & 15;
    int i0 = ty * 4, j0 = tx * 4;
    const int Ktot = DEMOd + Dd;  // 326
    u64 acc[2][4];
#pragma unroll
    for (int a = 0; a < 2; a++)
#pragma unroll
        for (int b = 0; b < 4; b++) acc[a][b] = splat2(0.f);
    for (int k0 = 0; k0 < 352; k0 += KC) {
        __syncthreads();
#pragma unroll
        for (int r = 0; r < 8; r++) {
            int idx = tid + r * 256;
            int iA = idx >> 5, kA = idx & 31;
            int kk = k0 + kA;
            float va = 0.f;
            if (kk < Ktot)
                va = (kk < DEMOd) ? demo[(r0 + iA) * DEMOd + kk]
                                  : g_R[(r0 + iA) * Dd + (kk - DEMOd)];
            As[kA * SST64 + iA] = va;
            int kB = idx >> 6, jB = idx & 63;
            int kk2 = k0 + kB;
            Bs[kB * SST64 + jB] = (kk2 < Ktot) ? W1[kk2 * HIDd + c0 + jB] : 0.f;
        }
        __syncthreads();
        mm4x4p(As, Bs, i0, j0, acc);
    }
#pragma unroll
    for (int a = 0; a < 2; a++)
#pragma unroll
        for (int b = 0; b < 4; b++) {
            float2 v = unpk(acc[a][b]);
            int col = c0 + j0 + b;
            float bb = b1[col];
            g_H[(r0 + i0 + 2 * a) * HIDd + col] = fmaxf(v.x + bb, 0.f);
            g_H[(r0 + i0 + 2 * a + 1) * HIDd + col] = fmaxf(v.y + bb, 0.f);
        }
}

// ---- K3c: per-sample logit + weighted BCE.  grid 256, 256 thr ----
__global__ __launch_bounds__(256) void k3c_loss(const float* __restrict__ W2,
                                                const float* __restrict__ b2,
                                                const float* __restrict__ labels) {
    int warp = threadIdx.x >> 5, lane = threadIdx.x & 31;
    int n = blockIdx.x * 8 + warp;
    float s = 0.f;
    for (int q = lane; q < HIDd; q += 32) s = fmaf(g_H[n * HIDd + q], W2[q], s);
#pragma unroll
    for (int o = 16; o; o >>= 1) s += __shfl_xor_sync(0xffffffffu, s, o);
    if (lane == 0) {
        float logit = s + b2[0];
        float y = labels[n];
        float sp = (logit > 0.f) ? logit + log1pf(expf(-logit)) : log1pf(expf(logit));
        float sp_neg = sp - logit;
        g_loss[n] = 2.0f * y * sp_neg + (1.0f - y) * sp;
    }
}

// ---- K4: deterministic reduce ----
__global__ __launch_bounds__(256) void k4_final(const float* __restrict__ c_attn,
                                                const float* __restrict__ c_pool,
                                                float* __restrict__ out) {
    __shared__ float red[256];
    int tid = threadIdx.x;
    float s = 0.f;
    for (int i = tid; i < Nn; i += 256) s += g_loss[i];
    red[tid] = s;
    __syncthreads();
    for (int st = 128; st; st >>= 1) {
        if (tid < st) red[tid] += red[tid + st];
        __syncthreads();
    }
    if (tid == 0) {
        float ca = c_attn[0], cp = c_pool[0];
        out[0] = red[0] / (float)Nn + ca * ca + cp * cp;
    }
}

static const int K2_SMEM = (Lh * Lh + 2 * KC * SST + 4 * Lh) * 4;  // ~101 KB

extern "C" void kernel_launch(void* const* d_in, const int* in_sizes, int n_in,
                              void* d_out, int out_size) {
    const float* E       = (const float*)d_in[0];
    const float* Wq      = (const float*)d_in[1];
    const float* Wk      = (const float*)d_in[2];
    const float* Wv      = (const float*)d_in[3];
    const float* c_attn  = (const float*)d_in[4];
    const float* c_pool  = (const float*)d_in[5];
    const float* W1      = (const float*)d_in[6];
    const float* b1      = (const float*)d_in[7];
    const float* W2      = (const float*)d_in[8];
    const float* b2      = (const float*)d_in[9];
    const float* demo    = (const float*)d_in[10];
    const float* ht      = (const float*)d_in[11];
    const float* et      = (const float*)d_in[12];
    const float* labels  = (const float*)d_in[13];
    const int*   codes   = (const int*)d_in[14];
    const int*   lengths = (const int*)d_in[15];
    float* out = (float*)d_out;

    cudaFuncSetAttribute(k2_attn, cudaFuncAttributeMaxDynamicSharedMemorySize, K2_SMEM);

    k0_M<<<dim3(4, 4), 256>>>(Wq, Wk);
    k1_EM<<<dim3(157, 2), 256>>>(E);
    k2_attn<<<Nn, 256, K2_SMEM>>>(E, codes, ht, et, lengths, c_attn, c_pool);
    k3a_R<<<dim3(32, 4), 256>>>(Wv);
    k3b_H<<<dim3(32, 16), 256>>>(demo, W1, b1);
    k3c_loss<<<Nn / 8, 256>>>(W2, b2, labels);
    k4_final<<<1, 256>>>(c_attn, c_pool, out);
}

// round 4
// speedup vs baseline: 3.4427x; 2.8467x over previous
#include <cuda_runtime.h>
#include <cuda_bf16.h>
#include <math.h>

#define Vv 20000
#define Lh 128
#define Dd 256
#define DEMOd 70
#define HIDd 1024
#define Nn 2048
#define KC 32
#define SST64 68   // fp32 64-wide smem panel stride
#define SA 136     // bf16 operand panel stride (136*2B = 272B, 16B-aligned)

typedef unsigned long long u64;
typedef unsigned int u32;

// ---------- fp32 packed helpers (kept for k0/k3a/k3b) ----------
__device__ __forceinline__ u64 ffma2(u64 a, u64 b, u64 c) {
    u64 d; asm("fma.rn.f32x2 %0,%1,%2,%3;" : "=l"(d) : "l"(a), "l"(b), "l"(c)); return d;
}
__device__ __forceinline__ u64 splat2(float x) {
    u64 d; asm("mov.b64 %0,{%1,%1};" : "=l"(d) : "f"(x)); return d;
}
__device__ __forceinline__ u64 pk(float x, float y) {
    u64 d; asm("mov.b64 %0,{%1,%2};" : "=l"(d) : "f"(x), "f"(y)); return d;
}
__device__ __forceinline__ float2 unpk(u64 v) {
    float2 r; asm("mov.b64 {%0,%1},%2;" : "=f"(r.x), "=f"(r.y) : "l"(v)); return r;
}
// pack two f32 -> bf16x2 (lo in low half)
__device__ __forceinline__ u32 pack_bf16(float lo, float hi) {
    u32 r; asm("cvt.rn.bf16x2.f32 %0, %1, %2;" : "=r"(r) : "f"(hi), "f"(lo)); return r;
}
// mma.sync m16n8k16 bf16, f32 accumulate (D += A*B)
__device__ __forceinline__ void mma_bf16(float* d, const u32* a, const u32* b) {
    asm volatile(
        "mma.sync.aligned.m16n8k16.row.col.f32.bf16.bf16.f32 "
        "{%0,%1,%2,%3},{%4,%5,%6,%7},{%8,%9},{%0,%1,%2,%3};"
        : "+f"(d[0]), "+f"(d[1]), "+f"(d[2]), "+f"(d[3])
        : "r"(a[0]), "r"(a[1]), "r"(a[2]), "r"(a[3]), "r"(b[0]), "r"(b[1]));
}

// ---------- device scratch ----------
__device__ __nv_bfloat16 g_E16[Vv * Dd];     // bf16 copy of E
__device__ __nv_bfloat16 g_EM16[Vv * Dd];    // bf16 (E @ Wq Wk^T / 16)
__device__ __nv_bfloat16 g_M16T[Dd * Dd];    // bf16 M^T: [n][k] = M[k][n]
__device__ float g_ebar[Nn * Dd];
__device__ float g_R[Nn * Dd];
__device__ float g_H[Nn * HIDd];
__device__ float g_loss[Nn];

// ---------- fp32 4x4 packed micro-kernel (64x64 tiles) ----------
__device__ __forceinline__ void mm4x4p(const float* As, const float* Bs,
                                       int i0, int j0, u64 acc[2][4]) {
#pragma unroll
    for (int k = 0; k < KC; k++) {
        float4 a0 = *(const float4*)(As + k * SST64 + i0);
        float4 b0 = *(const float4*)(Bs + k * SST64 + j0);
        u64 av[2] = {pk(a0.x, a0.y), pk(a0.z, a0.w)};
        float bv[4] = {b0.x, b0.y, b0.z, b0.w};
#pragma unroll
        for (int b = 0; b < 4; b++) {
            u64 bs = splat2(bv[b]);
#pragma unroll
            for (int a = 0; a < 2; a++) acc[a][b] = ffma2(av[a], bs, acc[a][b]);
        }
    }
}

// ---- Ke: E -> bf16.  grid 5000, 256 thr ----
__global__ __launch_bounds__(256) void k_e16(const float* __restrict__ E) {
    int idx = blockIdx.x * 256 + threadIdx.x;   // one float4 each
    float4 v = ((const float4*)E)[idx];
    uint2 o;
    o.x = pack_bf16(v.x, v.y);
    o.y = pack_bf16(v.z, v.w);
    ((uint2*)g_E16)[idx] = o;
}

// ---- K0: M16T = (Wq @ Wk^T / 16)^T in bf16.  grid (4,4), 256 thr ----
__global__ __launch_bounds__(256) void k0_M(const float* __restrict__ Wq,
                                            const float* __restrict__ Wk) {
    __shared__ float As[KC * SST64], Bs[KC * SST64];
    int r0 = blockIdx.x * 64, c0 = blockIdx.y * 64;
    int tid = threadIdx.x;
    int ty = tid >> 4, tx = tid & 15;
    int i0 = ty * 4, j0 = tx * 4;
    u64 acc[2][4];
#pragma unroll
    for (int a = 0; a < 2; a++)
#pragma unroll
        for (int b = 0; b < 4; b++) acc[a][b] = splat2(0.f);
    for (int k0 = 0; k0 < Dd; k0 += KC) {
        __syncthreads();
#pragma unroll
        for (int r = 0; r < 8; r++) {
            int idx = tid + r * 256;
            int i = idx >> 5, k = idx & 31;
            As[k * SST64 + i] = Wq[(r0 + i) * Dd + k0 + k];
            Bs[k * SST64 + i] = Wk[(c0 + i) * Dd + k0 + k];
        }
        __syncthreads();
        mm4x4p(As, Bs, i0, j0, acc);
    }
    const float sc = 1.0f / 16.0f;
#pragma unroll
    for (int a = 0; a < 2; a++)
#pragma unroll
        for (int b = 0; b < 4; b++) {
            float2 v = unpk(acc[a][b]);
            int row = r0 + i0 + 2 * a, col = c0 + j0 + b;
            g_M16T[col * Dd + row]     = __float2bfloat16(v.x * sc);
            g_M16T[col * Dd + row + 1] = __float2bfloat16(v.y * sc);
        }
}

// ---- K1: EM16 = E16 @ M (bf16 mma).  grid (157,2), 256 thr ----
__global__ __launch_bounds__(256, 2) void k1_EM() {
    extern __shared__ __align__(16) char smraw[];
    __nv_bfloat16* Asm = (__nv_bfloat16*)smraw;
    __nv_bfloat16* Bsm = Asm + 128 * SA;

    int r0 = blockIdx.x * 128, c0 = blockIdx.y * 128;
    int tid = threadIdx.x;
    int w = tid >> 5, lane = tid & 31;
    int g = lane >> 2, c4 = lane & 3;
    int warpRow = w * 16;

    float acc[16][4];
#pragma unroll
    for (int t = 0; t < 16; t++)
        acc[t][0] = acc[t][1] = acc[t][2] = acc[t][3] = 0.f;

    for (int p = 0; p < 2; p++) {
        __syncthreads();
#pragma unroll
        for (int it = 0; it < 8; it++) {
            int id = tid + it * 256;
            int row = id >> 4, seg = id & 15;
            int ra = r0 + row;
            uint4 va = make_uint4(0, 0, 0, 0);
            if (ra < Vv)
                va = ((const uint4*)(g_E16 + (size_t)ra * Dd + p * 128))[seg];
            uint4 vb = ((const uint4*)(g_M16T + (size_t)(c0 + row) * Dd + p * 128))[seg];
            *(uint4*)(Asm + row * SA + seg * 8) = va;
            *(uint4*)(Bsm + row * SA + seg * 8) = vb;
        }
        __syncthreads();
#pragma unroll
        for (int ks = 0; ks < 8; ks++) {
            int kb = ks * 16 + c4 * 2;
            u32 a[4];
            a[0] = *(const u32*)(Asm + (warpRow + g) * SA + kb);
            a[1] = *(const u32*)(Asm + (warpRow + g + 8) * SA + kb);
            a[2] = *(const u32*)(Asm + (warpRow + g) * SA + kb + 8);
            a[3] = *(const u32*)(Asm + (warpRow + g + 8) * SA + kb + 8);
#pragma unroll
            for (int nt = 0; nt < 16; nt++) {
                u32 b[2];
                int col = nt * 8 + g;
                b[0] = *(const u32*)(Bsm + col * SA + kb);
                b[1] = *(const u32*)(Bsm + col * SA + kb + 8);
                mma_bf16(acc[nt], a, b);
            }
        }
    }
    int rr0 = r0 + warpRow + g, rr1 = rr0 + 8;
#pragma unroll
    for (int nt = 0; nt < 16; nt++) {
        int cc = c0 + nt * 8 + c4 * 2;
        if (rr0 < Vv)
            *(u32*)(g_EM16 + (size_t)rr0 * Dd + cc) = pack_bf16(acc[nt][0], acc[nt][1]);
        if (rr1 < Vv)
            *(u32*)(g_EM16 + (size_t)rr1 * Dd + cc) = pack_bf16(acc[nt][2], acc[nt][3]);
    }
}

// ---- K2: per-sample attention (bf16 mma) + pooling -> g_ebar.  grid 2048, 256 thr ----
__global__ __launch_bounds__(256, 2) void k2_attn(
    const float* __restrict__ E, const int* __restrict__ codes,
    const float* __restrict__ ht, const float* __restrict__ et,
    const int* __restrict__ lengths, const float* __restrict__ c_attn,
    const float* __restrict__ c_pool) {
    extern __shared__ __align__(16) char smraw[];
    __nv_bfloat16* Asm = (__nv_bfloat16*)smraw;        // t = EM16 gather
    __nv_bfloat16* Bsm = Asm + 128 * SA;               // emb = E16 gather
    float* cs = (float*)(Bsm + 128 * SA);              // 8*128 partial colsums
    float* wv = cs + 8 * 128;                          // 128 pooling weights
    float* pv = wv + 128;                              // 128 col weights
    float* tv = pv + 128;                              // 128 hist times
    int*   cd = (int*)(tv + 128);                      // 128 codes

    int n = blockIdx.x, tid = threadIdx.x;
    int len = lengths[n];
    int w = tid >> 5, lane = tid & 31;
    int g = lane >> 2, c4 = lane & 3;

    if (tid < 128) {
        cd[tid] = codes[n * Lh + tid];
        tv[tid] = ht[n * Lh + tid];
        wv[tid] = 0.f;
    }
    __syncthreads();

    // pooling weights (args in [-10, 0] -> safe without max subtraction)
    if (tid < 32) {
        float cp = c_pool[0], e_t = et[n];
        float ssum = 0.f;
        for (int i = tid; i < len; i += 32) {
            float e = __expf(-cp * (e_t - tv[i]));
            wv[i] = e; ssum += e;
        }
#pragma unroll
        for (int o = 16; o; o >>= 1) ssum += __shfl_xor_sync(~0u, ssum, o);
        float inv = 1.f / ssum;
        for (int i = tid; i < len; i += 32) wv[i] *= inv;
    }

    int warpRow = w * 16;
    bool wact = warpRow < len;
    int lim = (len + 15) & ~15;

    float acc[16][4];
#pragma unroll
    for (int t = 0; t < 16; t++)
        acc[t][0] = acc[t][1] = acc[t][2] = acc[t][3] = 0.f;

    for (int p = 0; p < 2; p++) {
        __syncthreads();
#pragma unroll
        for (int it = 0; it < 8; it++) {
            int id = tid + it * 256;
            int row = id >> 4, seg = id & 15;
            if (row < lim) {
                uint4 va, vb;
                if (row < len) {
                    int c = cd[row];
                    va = ((const uint4*)(g_EM16 + (size_t)c * Dd + p * 128))[seg];
                    vb = ((const uint4*)(g_E16 + (size_t)c * Dd + p * 128))[seg];
                } else {
                    va = make_uint4(0, 0, 0, 0); vb = va;
                }
                *(uint4*)(Asm + row * SA + seg * 8) = va;
                *(uint4*)(Bsm + row * SA + seg * 8) = vb;
            }
        }
        __syncthreads();
        if (wact) {
#pragma unroll
            for (int ks = 0; ks < 8; ks++) {
                int kb = ks * 16 + c4 * 2;
                u32 a[4];
                a[0] = *(const u32*)(Asm + (warpRow + g) * SA + kb);
                a[1] = *(const u32*)(Asm + (warpRow + g + 8) * SA + kb);
                a[2] = *(const u32*)(Asm + (warpRow + g) * SA + kb + 8);
                a[3] = *(const u32*)(Asm + (warpRow + g + 8) * SA + kb + 8);
#pragma unroll
                for (int nt = 0; nt < 16; nt++) {
                    if (nt * 8 < len) {
                        u32 b[2];
                        int col = nt * 8 + g;
                        b[0] = *(const u32*)(Bsm + col * SA + kb);
                        b[1] = *(const u32*)(Bsm + col * SA + kb + 8);
                        mma_bf16(acc[nt], a, b);
                    }
                }
            }
        }
    }

    // in-register softmax (|s| <= ~1.1 -> no max subtraction) + w_i scaling
    float sc0 = 0.f, sc1 = 0.f;
    if (wact) {
        float ca = c_attn[0];
        int r0 = warpRow + g, r1 = r0 + 8;
        float ti0 = tv[r0], ti1 = tv[r1];
        float s0 = 0.f, s1 = 0.f;
#pragma unroll
        for (int nt = 0; nt < 16; nt++) {
            int j0 = nt * 8 + c4 * 2;
            if (nt * 8 < len) {
                float tj0 = tv[j0], tj1 = tv[j0 + 1];
                float e00 = (j0     < len) ? __expf(acc[nt][0] - ca * fabsf(ti0 - tj0)) : 0.f;
                float e01 = (j0 + 1 < len) ? __expf(acc[nt][1] - ca * fabsf(ti0 - tj1)) : 0.f;
                float e10 = (j0     < len) ? __expf(acc[nt][2] - ca * fabsf(ti1 - tj0)) : 0.f;
                float e11 = (j0 + 1 < len) ? __expf(acc[nt][3] - ca * fabsf(ti1 - tj1)) : 0.f;
                acc[nt][0] = e00; acc[nt][1] = e01; acc[nt][2] = e10; acc[nt][3] = e11;
                s0 += e00 + e01; s1 += e10 + e11;
            }
        }
        s0 += __shfl_xor_sync(~0u, s0, 1); s0 += __shfl_xor_sync(~0u, s0, 2);
        s1 += __shfl_xor_sync(~0u, s1, 1); s1 += __shfl_xor_sync(~0u, s1, 2);
        sc0 = wv[r0] / s0;          // wv=0 for invalid rows -> sc=0
        sc1 = wv[r1] / s1;
    }

    // column partials p_j (per warp), then cross-warp reduce
#pragma unroll
    for (int nt = 0; nt < 16; nt++) {
        float v0 = 0.f, v1 = 0.f;
        if (wact && nt * 8 < len) {
            v0 = acc[nt][0] * sc0 + acc[nt][2] * sc1;
            v1 = acc[nt][1] * sc0 + acc[nt][3] * sc1;
        }
        v0 += __shfl_xor_sync(~0u, v0, 4);  v1 += __shfl_xor_sync(~0u, v1, 4);
        v0 += __shfl_xor_sync(~0u, v0, 8);  v1 += __shfl_xor_sync(~0u, v1, 8);
        v0 += __shfl_xor_sync(~0u, v0, 16); v1 += __shfl_xor_sync(~0u, v1, 16);
        if (g == 0) {
            int j0 = nt * 8 + c4 * 2;
            cs[w * 128 + j0] = v0;
            cs[w * 128 + j0 + 1] = v1;
        }
    }
    __syncthreads();
    if (tid < 128) {
        float p = 0.f;
#pragma unroll
        for (int q = 0; q < 8; q++) p += cs[q * 128 + tid];
        pv[tid] = p;
    }
    __syncthreads();

    // ebar_d = sum_j p_j * E[cd_j][d]  (fp32 E for precision)
    float a = 0.f;
#pragma unroll 4
    for (int j = 0; j < len; j++)
        a = fmaf(pv[j], E[(size_t)cd[j] * Dd + tid], a);
    g_ebar[n * Dd + tid] = a;
}

// ---- K3a: R = ebar @ Wv.  fp32, 64x64 tiles, grid (32,4) ----
__global__ __launch_bounds__(256) void k3a_R(const float* __restrict__ Wv) {
    __shared__ float As[KC * SST64], Bs[KC * SST64];
    int r0 = blockIdx.x * 64, c0 = blockIdx.y * 64;
    int tid = threadIdx.x;
    int ty = tid >> 4, tx = tid & 15;
    int i0 = ty * 4, j0 = tx * 4;
    u64 acc[2][4];
#pragma unroll
    for (int a = 0; a < 2; a++)
#pragma unroll
        for (int b = 0; b < 4; b++) acc[a][b] = splat2(0.f);
    for (int k0 = 0; k0 < Dd; k0 += KC) {
        __syncthreads();
#pragma unroll
        for (int r = 0; r < 8; r++) {
            int idx = tid + r * 256;
            int iA = idx >> 5, kA = idx & 31;
            As[kA * SST64 + iA] = g_ebar[(r0 + iA) * Dd + k0 + kA];
            int kB = idx >> 6, jB = idx & 63;
            Bs[kB * SST64 + jB] = Wv[(k0 + kB) * Dd + c0 + jB];
        }
        __syncthreads();
        mm4x4p(As, Bs, i0, j0, acc);
    }
#pragma unroll
    for (int a = 0; a < 2; a++)
#pragma unroll
        for (int b = 0; b < 4; b++) {
            float2 v = unpk(acc[a][b]);
            g_R[(r0 + i0 + 2 * a) * Dd + c0 + j0 + b] = v.x;
            g_R[(r0 + i0 + 2 * a + 1) * Dd + c0 + j0 + b] = v.y;
        }
}

// ---- K3b: H = relu([demo, R] @ W1 + b1).  fp32, 64x64 tiles, grid (32,16) ----
__global__ __launch_bounds__(256) void k3b_H(const float* __restrict__ demo,
                                             const float* __restrict__ W1,
                                             const float* __restrict__ b1) {
    __shared__ float As[KC * SST64], Bs[KC * SST64];
    int r0 = blockIdx.x * 64, c0 = blockIdx.y * 64;
    int tid = threadIdx.x;
    int ty = tid >> 4, tx = tid & 15;
    int i0 = ty * 4, j0 = tx * 4;
    const int Ktot = DEMOd + Dd;
    u64 acc[2][4];
#pragma unroll
    for (int a = 0; a < 2; a++)
#pragma unroll
        for (int b = 0; b < 4; b++) acc[a][b] = splat2(0.f);
    for (int k0 = 0; k0 < 352; k0 += KC) {
        __syncthreads();
#pragma unroll
        for (int r = 0; r < 8; r++) {
            int idx = tid + r * 256;
            int iA = idx >> 5, kA = idx & 31;
            int kk = k0 + kA;
            float va = 0.f;
            if (kk < Ktot)
                va = (kk < DEMOd) ? demo[(r0 + iA) * DEMOd + kk]
                                  : g_R[(r0 + iA) * Dd + (kk - DEMOd)];
            As[kA * SST64 + iA] = va;
            int kB = idx >> 6, jB = idx & 63;
            int kk2 = k0 + kB;
            Bs[kB * SST64 + jB] = (kk2 < Ktot) ? W1[kk2 * HIDd + c0 + jB] : 0.f;
        }
        __syncthreads();
        mm4x4p(As, Bs, i0, j0, acc);
    }
#pragma unroll
    for (int a = 0; a < 2; a++)
#pragma unroll
        for (int b = 0; b < 4; b++) {
            float2 v = unpk(acc[a][b]);
            int col = c0 + j0 + b;
            float bb = b1[col];
            g_H[(r0 + i0 + 2 * a) * HIDd + col] = fmaxf(v.x + bb, 0.f);
            g_H[(r0 + i0 + 2 * a + 1) * HIDd + col] = fmaxf(v.y + bb, 0.f);
        }
}

// ---- K3c: per-sample logit + weighted BCE.  grid 256, 256 thr ----
__global__ __launch_bounds__(256) void k3c_loss(const float* __restrict__ W2,
                                                const float* __restrict__ b2,
                                                const float* __restrict__ labels) {
    int warp = threadIdx.x >> 5, lane = threadIdx.x & 31;
    int n = blockIdx.x * 8 + warp;
    float s = 0.f;
    for (int q = lane; q < HIDd; q += 32) s = fmaf(g_H[n * HIDd + q], W2[q], s);
#pragma unroll
    for (int o = 16; o; o >>= 1) s += __shfl_xor_sync(~0u, s, o);
    if (lane == 0) {
        float logit = s + b2[0];
        float y = labels[n];
        float sp = (logit > 0.f) ? logit + log1pf(expf(-logit)) : log1pf(expf(logit));
        float sp_neg = sp - logit;
        g_loss[n] = 2.0f * y * sp_neg + (1.0f - y) * sp;
    }
}

// ---- K4: deterministic reduce ----
__global__ __launch_bounds__(256) void k4_final(const float* __restrict__ c_attn,
                                                const float* __restrict__ c_pool,
                                                float* __restrict__ out) {
    __shared__ float red[256];
    int tid = threadIdx.x;
    float s = 0.f;
    for (int i = tid; i < Nn; i += 256) s += g_loss[i];
    red[tid] = s;
    __syncthreads();
    for (int st = 128; st; st >>= 1) {
        if (tid < st) red[tid] += red[tid + st];
        __syncthreads();
    }
    if (tid == 0) {
        float ca = c_attn[0], cp = c_pool[0];
        out[0] = red[0] / (float)Nn + ca * ca + cp * cp;
    }
}

static const int MMA_SMEM = 2 * 128 * SA * 2;                            // 69632
static const int K2_SMEM = MMA_SMEM + (8 * 128 + 3 * 128) * 4 + 128 * 4; // 75776

extern "C" void kernel_launch(void* const* d_in, const int* in_sizes, int n_in,
                              void* d_out, int out_size) {
    const float* E       = (const float*)d_in[0];
    const float* Wq      = (const float*)d_in[1];
    const float* Wk      = (const float*)d_in[2];
    const float* Wv      = (const float*)d_in[3];
    const float* c_attn  = (const float*)d_in[4];
    const float* c_pool  = (const float*)d_in[5];
    const float* W1      = (const float*)d_in[6];
    const float* b1      = (const float*)d_in[7];
    const float* W2      = (const float*)d_in[8];
    const float* b2      = (const float*)d_in[9];
    const float* demo    = (const float*)d_in[10];
    const float* ht      = (const float*)d_in[11];
    const float* et      = (const float*)d_in[12];
    const float* labels  = (const float*)d_in[13];
    const int*   codes   = (const int*)d_in[14];
    const int*   lengths = (const int*)d_in[15];
    float* out = (float*)d_out;

    cudaFuncSetAttribute(k1_EM, cudaFuncAttributeMaxDynamicSharedMemorySize, MMA_SMEM);
    cudaFuncSetAttribute(k2_attn, cudaFuncAttributeMaxDynamicSharedMemorySize, K2_SMEM);

    k_e16<<<Vv * Dd / 4 / 256, 256>>>(E);
    k0_M<<<dim3(4, 4), 256>>>(Wq, Wk);
    k1_EM<<<dim3(157, 2), 256, MMA_SMEM>>>();
    k2_attn<<<Nn, 256, K2_SMEM>>>(E, codes, ht, et, lengths, c_attn, c_pool);
    k3a_R<<<dim3(32, 4), 256>>>(Wv);
    k3b_H<<<dim3(32, 16), 256>>>(demo, W1, b1);
    k3c_loss<<<Nn / 8, 256>>>(W2, b2, labels);
    k4_final<<<1, 256>>>(c_attn, c_pool, out);
}

// round 5
// speedup vs baseline: 4.7034x; 1.3662x over previous
#include <cuda_runtime.h>
#include <cuda_bf16.h>
#include <math.h>

#define Vv 20000
#define Lh 128
#define Dd 256
#define DEMOd 70
#define HIDd 1024
#define Nn 2048
#define KC 32
#define SST64 68   // fp32 64-wide smem panel stride
#define SA 136     // bf16 operand panel stride (272B, 16B-aligned, conflict-free LDSM)
#define XK 384     // padded K for the MLP GEMM (70 demo + 256 repr + 58 zero)

typedef unsigned long long u64;
typedef unsigned int u32;

// ---------- fp32 packed helpers (k0 only) ----------
__device__ __forceinline__ u64 ffma2(u64 a, u64 b, u64 c) {
    u64 d; asm("fma.rn.f32x2 %0,%1,%2,%3;" : "=l"(d) : "l"(a), "l"(b), "l"(c)); return d;
}
__device__ __forceinline__ u64 splat2(float x) {
    u64 d; asm("mov.b64 %0,{%1,%1};" : "=l"(d) : "f"(x)); return d;
}
__device__ __forceinline__ u64 pk(float x, float y) {
    u64 d; asm("mov.b64 %0,{%1,%2};" : "=l"(d) : "f"(x), "f"(y)); return d;
}
__device__ __forceinline__ float2 unpk(u64 v) {
    float2 r; asm("mov.b64 {%0,%1},%2;" : "=f"(r.x), "=f"(r.y) : "l"(v)); return r;
}
__device__ __forceinline__ u32 pack_bf16(float lo, float hi) {
    u32 r; asm("cvt.rn.bf16x2.f32 %0, %1, %2;" : "=r"(r) : "f"(hi), "f"(lo)); return r;
}
__device__ __forceinline__ void mma_bf16(float* d, const u32* a, const u32* b) {
    asm volatile(
        "mma.sync.aligned.m16n8k16.row.col.f32.bf16.bf16.f32 "
        "{%0,%1,%2,%3},{%4,%5,%6,%7},{%8,%9},{%0,%1,%2,%3};"
        : "+f"(d[0]), "+f"(d[1]), "+f"(d[2]), "+f"(d[3])
        : "r"(a[0]), "r"(a[1]), "r"(a[2]), "r"(a[3]), "r"(b[0]), "r"(b[1]));
}
__device__ __forceinline__ void ldsm4(u32& r0, u32& r1, u32& r2, u32& r3, u32 a) {
    asm volatile("ldmatrix.sync.aligned.m8n8.x4.shared.b16 {%0,%1,%2,%3},[%4];"
                 : "=r"(r0), "=r"(r1), "=r"(r2), "=r"(r3) : "r"(a));
}
#define CP_ASYNC16(dst, src, sz) \
    asm volatile("cp.async.cg.shared.global [%0], [%1], 16, %2;" :: "r"(dst), "l"(src), "r"(sz))
#define CP_COMMIT() asm volatile("cp.async.commit_group;")
#define CP_WAIT0()  asm volatile("cp.async.wait_group 0;" ::: "memory")

// ---------- device scratch ----------
__device__ __nv_bfloat16 g_E16[Vv * Dd];
__device__ __nv_bfloat16 g_EM16[Vv * Dd];
__device__ __nv_bfloat16 g_M16T[Dd * Dd];
__device__ __nv_bfloat16 g_eb16[Nn * Dd];
__device__ __nv_bfloat16 g_WvT16[Dd * Dd];        // Wv^T  [n][k]
__device__ __nv_bfloat16 g_W1T16[HIDd * XK];      // W1^T padded  [h][k]
__device__ __nv_bfloat16 g_X16[Nn * XK];          // [demo | R | 0]
__device__ __nv_bfloat16 g_H16[Nn * HIDd];
__device__ float g_loss[Nn];
__device__ int g_perm[Nn];

// per-lane LDSM address offsets (elements) given warpRow
__device__ __forceinline__ u32 a_lane_off(int lane, int warpRow) {
    return (u32)((warpRow + (lane & 15)) * SA + ((lane >> 4) << 3));
}
__device__ __forceinline__ u32 b_lane_off(int lane) {
    return (u32)(((lane & 7) + ((lane >> 4) << 3)) * SA + (((lane >> 3) & 1) << 3));
}

// dense 128x128 panel mma (8 ksteps) via ldmatrix
__device__ __forceinline__ void mma_panel_dense(u32 aAddr, u32 bAddr, float acc[16][4]) {
#pragma unroll
    for (int ks = 0; ks < 8; ks++) {
        u32 a[4]; ldsm4(a[0], a[1], a[2], a[3], aAddr + ks * 32);
#pragma unroll
        for (int nt2 = 0; nt2 < 8; nt2++) {
            u32 b[4]; ldsm4(b[0], b[1], b[2], b[3], bAddr + nt2 * (16 * SA * 2) + ks * 32);
            mma_bf16(acc[2 * nt2], a, b);
            mma_bf16(acc[2 * nt2 + 1], a, b + 2);
        }
    }
}

// ---- sort: counting sort of sample ids by descending length (LPT) ----
__global__ __launch_bounds__(256) void k_sort(const int* __restrict__ lengths) {
    __shared__ int hist[129];
    __shared__ int base[129];
    int tid = threadIdx.x;
    for (int b = tid; b < 129; b += 256) hist[b] = 0;
    __syncthreads();
    for (int i = tid; i < Nn; i += 256) atomicAdd(&hist[128 - lengths[i]], 1);
    __syncthreads();
    if (tid == 0) { int s = 0; for (int b = 0; b < 129; b++) { base[b] = s; s += hist[b]; } }
    __syncthreads();
    for (int i = tid; i < Nn; i += 256) {
        int pos = atomicAdd(&base[128 - lengths[i]], 1);
        g_perm[pos] = i;
    }
}

// ---- Ke: E -> bf16 ----
__global__ __launch_bounds__(256) void k_e16(const float* __restrict__ E) {
    int idx = blockIdx.x * 256 + threadIdx.x;
    float4 v = ((const float4*)E)[idx];
    uint2 o;
    o.x = pack_bf16(v.x, v.y);
    o.y = pack_bf16(v.z, v.w);
    ((uint2*)g_E16)[idx] = o;
}

// ---- k_wvT: WvT16[n][k] = Wv[k][n]  (tiled transpose) ----
__global__ __launch_bounds__(256) void k_wvT(const float* __restrict__ Wv) {
    __shared__ float t[32][33];
    int tx = threadIdx.x & 31, ty = threadIdx.x >> 5;
    int k0 = blockIdx.x * 32, n0 = blockIdx.y * 32;
#pragma unroll
    for (int i = 0; i < 4; i++)
        t[ty + i * 8][tx] = Wv[(k0 + ty + i * 8) * Dd + n0 + tx];
    __syncthreads();
#pragma unroll
    for (int i = 0; i < 4; i++)
        g_WvT16[(n0 + ty + i * 8) * Dd + k0 + tx] = __float2bfloat16(t[tx][ty + i * 8]);
}

// ---- k_w1T: W1T16[h][k] = W1[k][h] (k<326, pad to 384) ----
__global__ __launch_bounds__(256) void k_w1T(const float* __restrict__ W1) {
    __shared__ float t[32][33];
    int tx = threadIdx.x & 31, ty = threadIdx.x >> 5;
    int k0 = blockIdx.x * 32, h0 = blockIdx.y * 32;
#pragma unroll
    for (int i = 0; i < 4; i++) {
        int k = k0 + ty + i * 8;
        t[ty + i * 8][tx] = (k < DEMOd + Dd) ? W1[k * HIDd + h0 + tx] : 0.f;
    }
    __syncthreads();
#pragma unroll
    for (int i = 0; i < 4; i++)
        g_W1T16[(h0 + ty + i * 8) * XK + k0 + tx] = __float2bfloat16(t[tx][ty + i * 8]);
}

// ---- k_x16: demo -> X cols [0,70), zero cols [326,384) ----
__global__ __launch_bounds__(128) void k_x16(const float* __restrict__ demo) {
    int r = blockIdx.x, t = threadIdx.x;
    if (t < DEMOd) g_X16[r * XK + t] = __float2bfloat16(demo[r * DEMOd + t]);
    else           g_X16[r * XK + 256 + t] = __float2bfloat16(0.f);   // 326..383
}

// ---- K0: M16T = (Wq @ Wk^T / 16)^T in bf16.  fp32 compute, grid (4,4) ----
__global__ __launch_bounds__(256) void k0_M(const float* __restrict__ Wq,
                                            const float* __restrict__ Wk) {
    __shared__ float As[KC * SST64], Bs[KC * SST64];
    int r0 = blockIdx.x * 64, c0 = blockIdx.y * 64;
    int tid = threadIdx.x;
    int ty = tid >> 4, tx = tid & 15;
    int i0 = ty * 4, j0 = tx * 4;
    u64 acc[2][4];
#pragma unroll
    for (int a = 0; a < 2; a++)
#pragma unroll
        for (int b = 0; b < 4; b++) acc[a][b] = splat2(0.f);
    for (int k0 = 0; k0 < Dd; k0 += KC) {
        __syncthreads();
#pragma unroll
        for (int r = 0; r < 8; r++) {
            int idx = tid + r * 256;
            int i = idx >> 5, k = idx & 31;
            As[k * SST64 + i] = Wq[(r0 + i) * Dd + k0 + k];
            Bs[k * SST64 + i] = Wk[(c0 + i) * Dd + k0 + k];
        }
        __syncthreads();
#pragma unroll
        for (int k = 0; k < KC; k++) {
            float4 a0 = *(const float4*)(As + k * SST64 + i0);
            float4 b0 = *(const float4*)(Bs + k * SST64 + j0);
            u64 av[2] = {pk(a0.x, a0.y), pk(a0.z, a0.w)};
            float bv[4] = {b0.x, b0.y, b0.z, b0.w};
#pragma unroll
            for (int b = 0; b < 4; b++) {
                u64 bs = splat2(bv[b]);
#pragma unroll
                for (int a = 0; a < 2; a++) acc[a][b] = ffma2(av[a], bs, acc[a][b]);
            }
        }
    }
    const float sc = 1.0f / 16.0f;
#pragma unroll
    for (int a = 0; a < 2; a++)
#pragma unroll
        for (int b = 0; b < 4; b++) {
            float2 v = unpk(acc[a][b]);
            int row = r0 + i0 + 2 * a, col = c0 + j0 + b;
            g_M16T[col * Dd + row]     = __float2bfloat16(v.x * sc);
            g_M16T[col * Dd + row + 1] = __float2bfloat16(v.y * sc);
        }
}

// ---- K1: EM16 = E16 @ M.  grid (157,2), ldmatrix + cp.async ----
__global__ __launch_bounds__(256, 2) void k1_EM() {
    extern __shared__ __align__(16) char smraw[];
    __nv_bfloat16* Asm = (__nv_bfloat16*)smraw;
    __nv_bfloat16* Bsm = Asm + 128 * SA;
    u32 smA = (u32)__cvta_generic_to_shared(Asm);
    u32 smB = (u32)__cvta_generic_to_shared(Bsm);

    int r0 = blockIdx.x * 128, c0 = blockIdx.y * 128;
    int tid = threadIdx.x;
    int w = tid >> 5, lane = tid & 31;
    int g = lane >> 2, c4 = lane & 3;
    int warpRow = w * 16;
    u32 aAddr = smA + a_lane_off(lane, warpRow) * 2;
    u32 bAddr = smB + b_lane_off(lane) * 2;

    float acc[16][4];
#pragma unroll
    for (int t = 0; t < 16; t++)
        acc[t][0] = acc[t][1] = acc[t][2] = acc[t][3] = 0.f;

    for (int p = 0; p < 2; p++) {
        __syncthreads();
#pragma unroll
        for (int it = 0; it < 8; it++) {
            int id = tid + it * 256;
            int row = id >> 4, seg = id & 15;
            int ra = r0 + row;
            const char* gA = (const char*)(g_E16 + (size_t)ra * Dd + p * 128) + seg * 16;
            const char* gB = (const char*)(g_M16T + (size_t)(c0 + row) * Dd + p * 128) + seg * 16;
            u32 sA = smA + (row * SA + seg * 8) * 2;
            u32 sB = smB + (row * SA + seg * 8) * 2;
            int sz = (ra < Vv) ? 16 : 0;
            CP_ASYNC16(sA, gA, sz);
            CP_ASYNC16(sB, gB, 16);
        }
        CP_COMMIT(); CP_WAIT0();
        __syncthreads();
        mma_panel_dense(aAddr, bAddr, acc);
    }
    int rr0 = r0 + warpRow + g, rr1 = rr0 + 8;
#pragma unroll
    for (int nt = 0; nt < 16; nt++) {
        int cc = c0 + nt * 8 + c4 * 2;
        if (rr0 < Vv)
            *(u32*)(g_EM16 + (size_t)rr0 * Dd + cc) = pack_bf16(acc[nt][0], acc[nt][1]);
        if (rr1 < Vv)
            *(u32*)(g_EM16 + (size_t)rr1 * Dd + cc) = pack_bf16(acc[nt][2], acc[nt][3]);
    }
}

// ---- K2: per-sample attention + pooling -> g_eb16.  grid 2048 ----
__global__ __launch_bounds__(256, 2) void k2_attn(
    const int* __restrict__ codes,
    const float* __restrict__ ht, const float* __restrict__ et,
    const int* __restrict__ lengths, const float* __restrict__ c_attn,
    const float* __restrict__ c_pool) {
    extern __shared__ __align__(16) char smraw[];
    __nv_bfloat16* Asm = (__nv_bfloat16*)smraw;        // t = EM16 gather
    __nv_bfloat16* Bsm = Asm + 128 * SA;               // emb = E16 gather
    float* cs = (float*)(Bsm + 128 * SA);              // 8*128 partial colsums
    float* wv = cs + 8 * 128;
    float* pv = wv + 128;
    float* tv = pv + 128;
    int*   cd = (int*)(tv + 128);
    u32 smA = (u32)__cvta_generic_to_shared(Asm);
    u32 smB = (u32)__cvta_generic_to_shared(Bsm);

    int n = g_perm[blockIdx.x];
    int tid = threadIdx.x;
    int len = lengths[n];
    int w = tid >> 5, lane = tid & 31;
    int g = lane >> 2, c4 = lane & 3;

    if (tid < 128) {
        cd[tid] = codes[n * Lh + tid];
        tv[tid] = ht[n * Lh + tid];
        wv[tid] = 0.f;
    }
    __syncthreads();

    if (tid < 32) {
        float cp = c_pool[0], e_t = et[n];
        float ssum = 0.f;
        for (int i = tid; i < len; i += 32) {
            float e = __expf(-cp * (e_t - tv[i]));
            wv[i] = e; ssum += e;
        }
#pragma unroll
        for (int o = 16; o; o >>= 1) ssum += __shfl_xor_sync(~0u, ssum, o);
        float inv = 1.f / ssum;
        for (int i = tid; i < len; i += 32) wv[i] *= inv;
    }

    int warpRow = w * 16;
    bool wact = warpRow < len;
    int lim = (len + 15) & ~15;
    int nt2max = (len + 15) >> 4;
    u32 aAddr = smA + a_lane_off(lane, warpRow) * 2;
    u32 bAddr = smB + b_lane_off(lane) * 2;

    float acc[16][4];
#pragma unroll
    for (int t = 0; t < 16; t++)
        acc[t][0] = acc[t][1] = acc[t][2] = acc[t][3] = 0.f;

    for (int p = 0; p < 2; p++) {
        __syncthreads();
#pragma unroll
        for (int it = 0; it < 8; it++) {
            int id = tid + it * 256;
            int row = id >> 4, seg = id & 15;
            if (row < lim) {
                int c = cd[row];
                const char* gA = (const char*)(g_EM16 + (size_t)c * Dd + p * 128) + seg * 16;
                const char* gB = (const char*)(g_E16 + (size_t)c * Dd + p * 128) + seg * 16;
                u32 sA = smA + (row * SA + seg * 8) * 2;
                u32 sB = smB + (row * SA + seg * 8) * 2;
                int sz = (row < len) ? 16 : 0;
                CP_ASYNC16(sA, gA, sz);
                CP_ASYNC16(sB, gB, sz);
            }
        }
        CP_COMMIT(); CP_WAIT0();
        __syncthreads();
        if (wact) {
#pragma unroll
            for (int ks = 0; ks < 8; ks++) {
                u32 a[4]; ldsm4(a[0], a[1], a[2], a[3], aAddr + ks * 32);
#pragma unroll
                for (int nt2 = 0; nt2 < 8; nt2++) {
                    if (nt2 < nt2max) {
                        u32 b[4];
                        ldsm4(b[0], b[1], b[2], b[3], bAddr + nt2 * (16 * SA * 2) + ks * 32);
                        mma_bf16(acc[2 * nt2], a, b);
                        if (nt2 * 16 + 8 < len) mma_bf16(acc[2 * nt2 + 1], a, b + 2);
                    }
                }
            }
        }
    }

    // in-register softmax (|s| small -> no max subtraction) + w_i scaling
    float sc0 = 0.f, sc1 = 0.f;
    if (wact) {
        float ca = c_attn[0];
        int r0 = warpRow + g, r1 = r0 + 8;
        float ti0 = tv[r0], ti1 = tv[r1];
        float s0 = 0.f, s1 = 0.f;
#pragma unroll
        for (int nt = 0; nt < 16; nt++) {
            int j0 = nt * 8 + c4 * 2;
            if (nt * 8 < len) {
                float tj0 = tv[j0], tj1 = tv[j0 + 1];
                float e00 = (j0     < len) ? __expf(acc[nt][0] - ca * fabsf(ti0 - tj0)) : 0.f;
                float e01 = (j0 + 1 < len) ? __expf(acc[nt][1] - ca * fabsf(ti0 - tj1)) : 0.f;
                float e10 = (j0     < len) ? __expf(acc[nt][2] - ca * fabsf(ti1 - tj0)) : 0.f;
                float e11 = (j0 + 1 < len) ? __expf(acc[nt][3] - ca * fabsf(ti1 - tj1)) : 0.f;
                acc[nt][0] = e00; acc[nt][1] = e01; acc[nt][2] = e10; acc[nt][3] = e11;
                s0 += e00 + e01; s1 += e10 + e11;
            }
        }
        s0 += __shfl_xor_sync(~0u, s0, 1); s0 += __shfl_xor_sync(~0u, s0, 2);
        s1 += __shfl_xor_sync(~0u, s1, 1); s1 += __shfl_xor_sync(~0u, s1, 2);
        sc0 = wv[r0] / s0;
        sc1 = wv[r1] / s1;
    }

    // column partials p_j
#pragma unroll
    for (int nt = 0; nt < 16; nt++) {
        float v0 = 0.f, v1 = 0.f;
        if (wact && nt * 8 < len) {
            v0 = acc[nt][0] * sc0 + acc[nt][2] * sc1;
            v1 = acc[nt][1] * sc0 + acc[nt][3] * sc1;
        }
        v0 += __shfl_xor_sync(~0u, v0, 4);  v1 += __shfl_xor_sync(~0u, v1, 4);
        v0 += __shfl_xor_sync(~0u, v0, 8);  v1 += __shfl_xor_sync(~0u, v1, 8);
        v0 += __shfl_xor_sync(~0u, v0, 16); v1 += __shfl_xor_sync(~0u, v1, 16);
        if (g == 0) {
            int j0 = nt * 8 + c4 * 2;
            cs[w * 128 + j0] = v0;
            cs[w * 128 + j0 + 1] = v1;
        }
    }
    __syncthreads();
    if (tid < 128) {
        float p = 0.f;
#pragma unroll
        for (int q = 0; q < 8; q++) p += cs[q * 128 + tid];
        pv[tid] = p;
    }
    __syncthreads();

    // ebar_d = sum_j p_j * E16[cd_j][d]  (fp32 accumulate)
    float a = 0.f;
#pragma unroll 4
    for (int j = 0; j < len; j++)
        a = fmaf(pv[j], __bfloat162float(g_E16[(size_t)cd[j] * Dd + tid]), a);
    g_eb16[n * Dd + tid] = __float2bfloat16(a);
}

// ---- K3a: R = eb16 @ Wv -> X cols [70,326).  grid (16,2) ----
__global__ __launch_bounds__(256, 2) void k3a_R() {
    extern __shared__ __align__(16) char smraw[];
    __nv_bfloat16* Asm = (__nv_bfloat16*)smraw;
    __nv_bfloat16* Bsm = Asm + 128 * SA;
    u32 smA = (u32)__cvta_generic_to_shared(Asm);
    u32 smB = (u32)__cvta_generic_to_shared(Bsm);

    int r0 = blockIdx.x * 128, c0 = blockIdx.y * 128;
    int tid = threadIdx.x;
    int w = tid >> 5, lane = tid & 31;
    int g = lane >> 2, c4 = lane & 3;
    int warpRow = w * 16;
    u32 aAddr = smA + a_lane_off(lane, warpRow) * 2;
    u32 bAddr = smB + b_lane_off(lane) * 2;

    float acc[16][4];
#pragma unroll
    for (int t = 0; t < 16; t++)
        acc[t][0] = acc[t][1] = acc[t][2] = acc[t][3] = 0.f;

    for (int p = 0; p < 2; p++) {
        __syncthreads();
#pragma unroll
        for (int it = 0; it < 8; it++) {
            int id = tid + it * 256;
            int row = id >> 4, seg = id & 15;
            const char* gA = (const char*)(g_eb16 + (size_t)(r0 + row) * Dd + p * 128) + seg * 16;
            const char* gB = (const char*)(g_WvT16 + (size_t)(c0 + row) * Dd + p * 128) + seg * 16;
            CP_ASYNC16(smA + (row * SA + seg * 8) * 2, gA, 16);
            CP_ASYNC16(smB + (row * SA + seg * 8) * 2, gB, 16);
        }
        CP_COMMIT(); CP_WAIT0();
        __syncthreads();
        mma_panel_dense(aAddr, bAddr, acc);
    }
    int rr0 = r0 + warpRow + g, rr1 = rr0 + 8;
#pragma unroll
    for (int nt = 0; nt < 16; nt++) {
        int cc = DEMOd + c0 + nt * 8 + c4 * 2;   // 70 + col (even -> 4B aligned)
        *(u32*)(g_X16 + (size_t)rr0 * XK + cc) = pack_bf16(acc[nt][0], acc[nt][1]);
        *(u32*)(g_X16 + (size_t)rr1 * XK + cc) = pack_bf16(acc[nt][2], acc[nt][3]);
    }
}

// ---- K3b: H16 = relu(X16 @ W1 + b1).  grid (16,8), K=384 (3 panels) ----
__global__ __launch_bounds__(256, 2) void k3b_H(const float* __restrict__ b1) {
    extern __shared__ __align__(16) char smraw[];
    __nv_bfloat16* Asm = (__nv_bfloat16*)smraw;
    __nv_bfloat16* Bsm = Asm + 128 * SA;
    u32 smA = (u32)__cvta_generic_to_shared(Asm);
    u32 smB = (u32)__cvta_generic_to_shared(Bsm);

    int r0 = blockIdx.x * 128, c0 = blockIdx.y * 128;
    int tid = threadIdx.x;
    int w = tid >> 5, lane = tid & 31;
    int g = lane >> 2, c4 = lane & 3;
    int warpRow = w * 16;
    u32 aAddr = smA + a_lane_off(lane, warpRow) * 2;
    u32 bAddr = smB + b_lane_off(lane) * 2;

    float acc[16][4];
#pragma unroll
    for (int t = 0; t < 16; t++)
        acc[t][0] = acc[t][1] = acc[t][2] = acc[t][3] = 0.f;

    for (int p = 0; p < 3; p++) {
        __syncthreads();
#pragma unroll
        for (int it = 0; it < 8; it++) {
            int id = tid + it * 256;
            int row = id >> 4, seg = id & 15;
            const char* gA = (const char*)(g_X16 + (size_t)(r0 + row) * XK + p * 128) + seg * 16;
            const char* gB = (const char*)(g_W1T16 + (size_t)(c0 + row) * XK + p * 128) + seg * 16;
            CP_ASYNC16(smA + (row * SA + seg * 8) * 2, gA, 16);
            CP_ASYNC16(smB + (row * SA + seg * 8) * 2, gB, 16);
        }
        CP_COMMIT(); CP_WAIT0();
        __syncthreads();
        mma_panel_dense(aAddr, bAddr, acc);
    }
    int rr0 = r0 + warpRow + g, rr1 = rr0 + 8;
#pragma unroll
    for (int nt = 0; nt < 16; nt++) {
        int col = c0 + nt * 8 + c4 * 2;
        float b0 = b1[col], b1v = b1[col + 1];
        *(u32*)(g_H16 + (size_t)rr0 * HIDd + col) =
            pack_bf16(fmaxf(acc[nt][0] + b0, 0.f), fmaxf(acc[nt][1] + b1v, 0.f));
        *(u32*)(g_H16 + (size_t)rr1 * HIDd + col) =
            pack_bf16(fmaxf(acc[nt][2] + b0, 0.f), fmaxf(acc[nt][3] + b1v, 0.f));
    }
}

// ---- K3c: logit + weighted BCE ----
__global__ __launch_bounds__(256) void k3c_loss(const float* __restrict__ W2,
                                                const float* __restrict__ b2,
                                                const float* __restrict__ labels) {
    int warp = threadIdx.x >> 5, lane = threadIdx.x & 31;
    int n = blockIdx.x * 8 + warp;
    float s = 0.f;
    for (int q = lane; q < HIDd; q += 32)
        s = fmaf(__bfloat162float(g_H16[(size_t)n * HIDd + q]), W2[q], s);
#pragma unroll
    for (int o = 16; o; o >>= 1) s += __shfl_xor_sync(~0u, s, o);
    if (lane == 0) {
        float logit = s + b2[0];
        float y = labels[n];
        float sp = (logit > 0.f) ? logit + log1pf(expf(-logit)) : log1pf(expf(logit));
        float sp_neg = sp - logit;
        g_loss[n] = 2.0f * y * sp_neg + (1.0f - y) * sp;
    }
}

// ---- K4: deterministic reduce ----
__global__ __launch_bounds__(256) void k4_final(const float* __restrict__ c_attn,
                                                const float* __restrict__ c_pool,
                                                float* __restrict__ out) {
    __shared__ float red[256];
    int tid = threadIdx.x;
    float s = 0.f;
    for (int i = tid; i < Nn; i += 256) s += g_loss[i];
    red[tid] = s;
    __syncthreads();
    for (int st = 128; st; st >>= 1) {
        if (tid < st) red[tid] += red[tid + st];
        __syncthreads();
    }
    if (tid == 0) {
        float ca = c_attn[0], cp = c_pool[0];
        out[0] = red[0] / (float)Nn + ca * ca + cp * cp;
    }
}

static const int MMA_SMEM = 2 * 128 * SA * 2;                            // 69632
static const int K2_SMEM = MMA_SMEM + (8 * 128 + 3 * 128) * 4 + 128 * 4; // 75776

extern "C" void kernel_launch(void* const* d_in, const int* in_sizes, int n_in,
                              void* d_out, int out_size) {
    const float* E       = (const float*)d_in[0];
    const float* Wq      = (const float*)d_in[1];
    const float* Wk      = (const float*)d_in[2];
    const float* Wv      = (const float*)d_in[3];
    const float* c_attn  = (const float*)d_in[4];
    const float* c_pool  = (const float*)d_in[5];
    const float* W1      = (const float*)d_in[6];
    const float* b1      = (const float*)d_in[7];
    const float* W2      = (const float*)d_in[8];
    const float* b2      = (const float*)d_in[9];
    const float* demo    = (const float*)d_in[10];
    const float* ht      = (const float*)d_in[11];
    const float* et      = (const float*)d_in[12];
    const float* labels  = (const float*)d_in[13];
    const int*   codes   = (const int*)d_in[14];
    const int*   lengths = (const int*)d_in[15];
    float* out = (float*)d_out;

    cudaFuncSetAttribute(k1_EM, cudaFuncAttributeMaxDynamicSharedMemorySize, MMA_SMEM);
    cudaFuncSetAttribute(k2_attn, cudaFuncAttributeMaxDynamicSharedMemorySize, K2_SMEM);
    cudaFuncSetAttribute(k3a_R, cudaFuncAttributeMaxDynamicSharedMemorySize, MMA_SMEM);
    cudaFuncSetAttribute(k3b_H, cudaFuncAttributeMaxDynamicSharedMemorySize, MMA_SMEM);

    k_sort<<<1, 256>>>(lengths);
    k_e16<<<Vv * Dd / 4 / 256, 256>>>(E);
    k_wvT<<<dim3(8, 8), 256>>>(Wv);
    k_w1T<<<dim3(12, 32), 256>>>(W1);
    k_x16<<<Nn, 128>>>(demo);
    k0_M<<<dim3(4, 4), 256>>>(Wq, Wk);
    k1_EM<<<dim3(157, 2), 256, MMA_SMEM>>>();
    k2_attn<<<Nn, 256, K2_SMEM>>>(codes, ht, et, lengths, c_attn, c_pool);
    k3a_R<<<dim3(16, 2), 256, MMA_SMEM>>>();
    k3b_H<<<dim3(16, 8), 256, MMA_SMEM>>>(b1);
    k3c_loss<<<Nn / 8, 256>>>(W2, b2, labels);
    k4_final<<<1, 256>>>(c_attn, c_pool, out);
}

// round 6
// speedup vs baseline: 5.7033x; 1.2126x over previous
#include <cuda_runtime.h>
#include <cuda_bf16.h>
#include <math.h>

#define Vv 20000
#define Lh 128
#define Dd 256
#define DEMOd 70
#define HIDd 1024
#define Nn 2048
#define KC 32
#define SST64 68
#define SA 136     // bf16 operand panel stride (272B, 16B-aligned, conflict-free LDSM)
#define XK 384

typedef unsigned long long u64;
typedef unsigned int u32;

__device__ __forceinline__ u64 ffma2(u64 a, u64 b, u64 c) {
    u64 d; asm("fma.rn.f32x2 %0,%1,%2,%3;" : "=l"(d) : "l"(a), "l"(b), "l"(c)); return d;
}
__device__ __forceinline__ u64 splat2(float x) {
    u64 d; asm("mov.b64 %0,{%1,%1};" : "=l"(d) : "f"(x)); return d;
}
__device__ __forceinline__ u64 pk(float x, float y) {
    u64 d; asm("mov.b64 %0,{%1,%2};" : "=l"(d) : "f"(x), "f"(y)); return d;
}
__device__ __forceinline__ float2 unpk(u64 v) {
    float2 r; asm("mov.b64 {%0,%1},%2;" : "=f"(r.x), "=f"(r.y) : "l"(v)); return r;
}
__device__ __forceinline__ u32 pack_bf16(float lo, float hi) {
    u32 r; asm("cvt.rn.bf16x2.f32 %0, %1, %2;" : "=r"(r) : "f"(hi), "f"(lo)); return r;
}
__device__ __forceinline__ void mma_bf16(float* d, const u32* a, const u32* b) {
    asm volatile(
        "mma.sync.aligned.m16n8k16.row.col.f32.bf16.bf16.f32 "
        "{%0,%1,%2,%3},{%4,%5,%6,%7},{%8,%9},{%0,%1,%2,%3};"
        : "+f"(d[0]), "+f"(d[1]), "+f"(d[2]), "+f"(d[3])
        : "r"(a[0]), "r"(a[1]), "r"(a[2]), "r"(a[3]), "r"(b[0]), "r"(b[1]));
}
__device__ __forceinline__ void ldsm4(u32& r0, u32& r1, u32& r2, u32& r3, u32 a) {
    asm volatile("ldmatrix.sync.aligned.m8n8.x4.shared.b16 {%0,%1,%2,%3},[%4];"
                 : "=r"(r0), "=r"(r1), "=r"(r2), "=r"(r3) : "r"(a));
}
#define CP_ASYNC16(dst, src, sz) \
    asm volatile("cp.async.cg.shared.global [%0], [%1], 16, %2;" :: "r"(dst), "l"(src), "r"(sz))
#define CP_COMMIT() asm volatile("cp.async.commit_group;")
#define CP_WAIT0()  asm volatile("cp.async.wait_group 0;" ::: "memory")
#define CP_WAIT1()  asm volatile("cp.async.wait_group 1;" ::: "memory")

// ---------- device scratch ----------
__device__ __nv_bfloat16 g_E16[Vv * Dd];
__device__ __nv_bfloat16 g_EM16[Vv * Dd];
__device__ __nv_bfloat16 g_M16T[Dd * Dd];
__device__ __nv_bfloat16 g_eb16[Nn * Dd];
__device__ __nv_bfloat16 g_WvT16[Dd * Dd];
__device__ __nv_bfloat16 g_W1T16[HIDd * XK];
__device__ __nv_bfloat16 g_X16[Nn * XK];
__device__ __nv_bfloat16 g_H16[Nn * HIDd];
__device__ float g_loss[Nn];
__device__ int g_perm[Nn];

__device__ __forceinline__ u32 a_lane_off(int lane, int warpRow) {
    return (u32)((warpRow + (lane & 15)) * SA + ((lane >> 4) << 3));
}
__device__ __forceinline__ u32 b_lane_off(int lane) {
    return (u32)(((lane & 7) + ((lane >> 4) << 3)) * SA + (((lane >> 3) & 1) << 3));
}

// dense ksteps [ks0,ks1) over full 128-col B panel
__device__ __forceinline__ void mma_ks_dense(u32 aAddr, u32 bAddr, float acc[16][4],
                                             int ks0, int ks1) {
    for (int ks = ks0; ks < ks1; ks++) {
        u32 a[4]; ldsm4(a[0], a[1], a[2], a[3], aAddr + ks * 32);
#pragma unroll
        for (int nt2 = 0; nt2 < 8; nt2++) {
            u32 b[4]; ldsm4(b[0], b[1], b[2], b[3], bAddr + nt2 * (16 * SA * 2) + ks * 32);
            mma_bf16(acc[2 * nt2], a, b);
            mma_bf16(acc[2 * nt2 + 1], a, b + 2);
        }
    }
}

// ============ merged prep kernel ============
// blocks: [0,16) k0_M | [16,5016) e16 | [5016,5080) wvT | [5080,5464) w1T
//         [5464,6488) x16 (2 rows/blk) | 6488 sort
__global__ __launch_bounds__(256) void k_prep(
    const float* __restrict__ E, const float* __restrict__ Wq,
    const float* __restrict__ Wk, const float* __restrict__ Wv,
    const float* __restrict__ W1, const float* __restrict__ demo,
    const int* __restrict__ lengths) {
    extern __shared__ __align__(16) char psm[];
    int b = blockIdx.x, tid = threadIdx.x;

    if (b < 16) {                     // ---- k0: M16T = (Wq Wk^T / 16)^T bf16
        float* As = (float*)psm;
        float* Bs = As + KC * SST64;
        int r0 = (b & 3) * 64, c0 = (b >> 2) * 64;
        int ty = tid >> 4, tx = tid & 15;
        int i0 = ty * 4, j0 = tx * 4;
        u64 acc[2][4];
#pragma unroll
        for (int a = 0; a < 2; a++)
#pragma unroll
            for (int c = 0; c < 4; c++) acc[a][c] = splat2(0.f);
        for (int k0 = 0; k0 < Dd; k0 += KC) {
            __syncthreads();
#pragma unroll
            for (int r = 0; r < 8; r++) {
                int idx = tid + r * 256;
                int i = idx >> 5, k = idx & 31;
                As[k * SST64 + i] = Wq[(r0 + i) * Dd + k0 + k];
                Bs[k * SST64 + i] = Wk[(c0 + i) * Dd + k0 + k];
            }
            __syncthreads();
#pragma unroll
            for (int k = 0; k < KC; k++) {
                float4 a0 = *(const float4*)(As + k * SST64 + i0);
                float4 b0 = *(const float4*)(Bs + k * SST64 + j0);
                u64 av[2] = {pk(a0.x, a0.y), pk(a0.z, a0.w)};
                float bv[4] = {b0.x, b0.y, b0.z, b0.w};
#pragma unroll
                for (int cc = 0; cc < 4; cc++) {
                    u64 bs = splat2(bv[cc]);
#pragma unroll
                    for (int a = 0; a < 2; a++) acc[a][cc] = ffma2(av[a], bs, acc[a][cc]);
                }
            }
        }
        const float sc = 1.0f / 16.0f;
#pragma unroll
        for (int a = 0; a < 2; a++)
#pragma unroll
            for (int c = 0; c < 4; c++) {
                float2 v = unpk(acc[a][c]);
                int row = r0 + i0 + 2 * a, col = c0 + j0 + c;
                g_M16T[col * Dd + row]     = __float2bfloat16(v.x * sc);
                g_M16T[col * Dd + row + 1] = __float2bfloat16(v.y * sc);
            }
    } else if (b < 5016) {            // ---- e16
        int idx = (b - 16) * 256 + tid;
        float4 v = ((const float4*)E)[idx];
        uint2 o;
        o.x = pack_bf16(v.x, v.y);
        o.y = pack_bf16(v.z, v.w);
        ((uint2*)g_E16)[idx] = o;
    } else if (b < 5080) {            // ---- wvT
        float* t = (float*)psm;       // 32*33
        int local = b - 5016;
        int k0 = (local & 7) * 32, n0 = (local >> 3) * 32;
        int tx = tid & 31, ty = tid >> 5;
#pragma unroll
        for (int i = 0; i < 4; i++)
            t[(ty + i * 8) * 33 + tx] = Wv[(k0 + ty + i * 8) * Dd + n0 + tx];
        __syncthreads();
#pragma unroll
        for (int i = 0; i < 4; i++)
            g_WvT16[(n0 + ty + i * 8) * Dd + k0 + tx] = __float2bfloat16(t[tx * 33 + ty + i * 8]);
    } else if (b < 5464) {            // ---- w1T
        float* t = (float*)psm;
        int local = b - 5080;
        int k0 = (local % 12) * 32, h0 = (local / 12) * 32;
        int tx = tid & 31, ty = tid >> 5;
#pragma unroll
        for (int i = 0; i < 4; i++) {
            int k = k0 + ty + i * 8;
            t[(ty + i * 8) * 33 + tx] = (k < DEMOd + Dd) ? W1[k * HIDd + h0 + tx] : 0.f;
        }
        __syncthreads();
#pragma unroll
        for (int i = 0; i < 4; i++)
            g_W1T16[(h0 + ty + i * 8) * XK + k0 + tx] = __float2bfloat16(t[tx * 33 + ty + i * 8]);
    } else if (b < 6488) {            // ---- x16 (2 rows per block)
        int local = b - 5464;
        int r = local * 2 + (tid >> 7);
        int t = tid & 127;
        if (t < DEMOd) g_X16[r * XK + t] = __float2bfloat16(demo[r * DEMOd + t]);
        else           g_X16[r * XK + 256 + t] = __float2bfloat16(0.f);
    } else {                          // ---- sort (LPT permutation)
        __shared__ int hist[129], base[129];
        for (int c = tid; c < 129; c += 256) hist[c] = 0;
        __syncthreads();
        for (int i = tid; i < Nn; i += 256) atomicAdd(&hist[128 - lengths[i]], 1);
        __syncthreads();
        if (tid == 0) { int s = 0; for (int c = 0; c < 129; c++) { base[c] = s; s += hist[c]; } }
        __syncthreads();
        for (int i = tid; i < Nn; i += 256) {
            int pos = atomicAdd(&base[128 - lengths[i]], 1);
            g_perm[pos] = i;
        }
    }
}

// ---- K1: EM16 = E16 @ M.  grid (157,2), split-wait pipeline ----
__global__ __launch_bounds__(256, 2) void k1_EM() {
    extern __shared__ __align__(16) char smraw[];
    __nv_bfloat16* Asm = (__nv_bfloat16*)smraw;
    __nv_bfloat16* Bsm = Asm + 128 * SA;
    u32 smA = (u32)__cvta_generic_to_shared(Asm);
    u32 smB = (u32)__cvta_generic_to_shared(Bsm);

    int r0 = blockIdx.x * 128, c0 = blockIdx.y * 128;
    int tid = threadIdx.x;
    int w = tid >> 5, lane = tid & 31;
    int g = lane >> 2, c4 = lane & 3;
    int warpRow = w * 16;
    u32 aAddr = smA + a_lane_off(lane, warpRow) * 2;
    u32 bAddr = smB + b_lane_off(lane) * 2;

    float acc[16][4];
#pragma unroll
    for (int t = 0; t < 16; t++)
        acc[t][0] = acc[t][1] = acc[t][2] = acc[t][3] = 0.f;

    for (int p = 0; p < 2; p++) {
        __syncthreads();
#pragma unroll
        for (int half = 0; half < 2; half++) {
#pragma unroll
            for (int it = 0; it < 4; it++) {
                int id = tid + it * 256;
                int row = id >> 3, seg = (id & 7) + half * 8;
                int ra = r0 + row;
                const char* gA = (const char*)(g_E16 + (size_t)ra * Dd + p * 128) + seg * 16;
                const char* gB = (const char*)(g_M16T + (size_t)(c0 + row) * Dd + p * 128) + seg * 16;
                u32 off = (u32)(row * SA + seg * 8) * 2;
                CP_ASYNC16(smA + off, gA, (ra < Vv) ? 16 : 0);
                CP_ASYNC16(smB + off, gB, 16);
            }
            CP_COMMIT();
        }
        CP_WAIT1();
        __syncthreads();
        mma_ks_dense(aAddr, bAddr, acc, 0, 4);
        CP_WAIT0();
        __syncthreads();
        mma_ks_dense(aAddr, bAddr, acc, 4, 8);
    }
    int rr0 = r0 + warpRow + g, rr1 = rr0 + 8;
#pragma unroll
    for (int nt = 0; nt < 16; nt++) {
        int cc = c0 + nt * 8 + c4 * 2;
        if (rr0 < Vv)
            *(u32*)(g_EM16 + (size_t)rr0 * Dd + cc) = pack_bf16(acc[nt][0], acc[nt][1]);
        if (rr1 < Vv)
            *(u32*)(g_EM16 + (size_t)rr1 * Dd + cc) = pack_bf16(acc[nt][2], acc[nt][3]);
    }
}

// ---- K2: per-sample attention + pooling.  grid 2048, split-wait + smem ebar ----
__global__ __launch_bounds__(256, 2) void k2_attn(
    const int* __restrict__ codes,
    const float* __restrict__ ht, const float* __restrict__ et,
    const int* __restrict__ lengths, const float* __restrict__ c_attn,
    const float* __restrict__ c_pool) {
    extern __shared__ __align__(16) char smraw[];
    __nv_bfloat16* Asm = (__nv_bfloat16*)smraw;
    __nv_bfloat16* Bsm = Asm + 128 * SA;
    float* cs = (float*)(Bsm + 128 * SA);
    float* wv = cs + 8 * 128;
    float* pv = wv + 128;
    float* tv = pv + 128;
    int*   cd = (int*)(tv + 128);
    u32 smA = (u32)__cvta_generic_to_shared(Asm);
    u32 smB = (u32)__cvta_generic_to_shared(Bsm);

    int n = g_perm[blockIdx.x];
    int tid = threadIdx.x;
    int len = lengths[n];
    int w = tid >> 5, lane = tid & 31;
    int g = lane >> 2, c4 = lane & 3;

    if (tid < 128) {
        cd[tid] = codes[n * Lh + tid];
        tv[tid] = ht[n * Lh + tid];
        wv[tid] = 0.f;
    }
    __syncthreads();

    if (tid < 32) {
        float cp = c_pool[0], e_t = et[n];
        float ssum = 0.f;
        for (int i = tid; i < len; i += 32) {
            float e = __expf(-cp * (e_t - tv[i]));
            wv[i] = e; ssum += e;
        }
#pragma unroll
        for (int o = 16; o; o >>= 1) ssum += __shfl_xor_sync(~0u, ssum, o);
        float inv = 1.f / ssum;
        for (int i = tid; i < len; i += 32) wv[i] *= inv;
    }

    int warpRow = w * 16;
    bool wact = warpRow < len;
    int lim = (len + 15) & ~15;
    int nt2max = (len + 15) >> 4;
    u32 aAddr = smA + a_lane_off(lane, warpRow) * 2;
    u32 bAddr = smB + b_lane_off(lane) * 2;

    float acc[16][4];
#pragma unroll
    for (int t = 0; t < 16; t++)
        acc[t][0] = acc[t][1] = acc[t][2] = acc[t][3] = 0.f;

    for (int p = 0; p < 2; p++) {
        __syncthreads();
#pragma unroll
        for (int half = 0; half < 2; half++) {
#pragma unroll
            for (int it = 0; it < 4; it++) {
                int id = tid + it * 256;
                int row = id >> 3, seg = (id & 7) + half * 8;
                if (row < lim) {
                    int c = cd[row];
                    const char* gA = (const char*)(g_EM16 + (size_t)c * Dd + p * 128) + seg * 16;
                    const char* gB = (const char*)(g_E16 + (size_t)c * Dd + p * 128) + seg * 16;
                    u32 off = (u32)(row * SA + seg * 8) * 2;
                    int sz = (row < len) ? 16 : 0;
                    CP_ASYNC16(smA + off, gA, sz);
                    CP_ASYNC16(smB + off, gB, sz);
                }
            }
            CP_COMMIT();
        }
        CP_WAIT1();
        __syncthreads();
        if (wact) {
            for (int ks = 0; ks < 4; ks++) {
                u32 a[4]; ldsm4(a[0], a[1], a[2], a[3], aAddr + ks * 32);
#pragma unroll
                for (int nt2 = 0; nt2 < 8; nt2++) {
                    if (nt2 < nt2max) {
                        u32 b[4];
                        ldsm4(b[0], b[1], b[2], b[3], bAddr + nt2 * (16 * SA * 2) + ks * 32);
                        mma_bf16(acc[2 * nt2], a, b);
                        if (nt2 * 16 + 8 < len) mma_bf16(acc[2 * nt2 + 1], a, b + 2);
                    }
                }
            }
        }
        CP_WAIT0();
        __syncthreads();
        if (wact) {
            for (int ks = 4; ks < 8; ks++) {
                u32 a[4]; ldsm4(a[0], a[1], a[2], a[3], aAddr + ks * 32);
#pragma unroll
                for (int nt2 = 0; nt2 < 8; nt2++) {
                    if (nt2 < nt2max) {
                        u32 b[4];
                        ldsm4(b[0], b[1], b[2], b[3], bAddr + nt2 * (16 * SA * 2) + ks * 32);
                        mma_bf16(acc[2 * nt2], a, b);
                        if (nt2 * 16 + 8 < len) mma_bf16(acc[2 * nt2 + 1], a, b + 2);
                    }
                }
            }
        }
    }

    // reload E16 k-half0 into Asm (overlapped with softmax below).
    __syncthreads();   // all warps done reading Asm
#pragma unroll
    for (int it = 0; it < 8; it++) {
        int id = tid + it * 256;
        int row = id >> 4, seg = id & 15;
        if (row < lim) {
            int c = cd[row];
            const char* gB = (const char*)(g_E16 + (size_t)c * Dd) + seg * 16;
            int sz = (row < len) ? 16 : 0;
            CP_ASYNC16(smA + (u32)(row * SA + seg * 8) * 2, gB, sz);
        }
    }
    CP_COMMIT();

    // in-register softmax + w_i scaling
    float sc0 = 0.f, sc1 = 0.f;
    if (wact) {
        float ca = c_attn[0];
        int r0 = warpRow + g, r1 = r0 + 8;
        float ti0 = tv[r0], ti1 = tv[r1];
        float s0 = 0.f, s1 = 0.f;
#pragma unroll
        for (int nt = 0; nt < 16; nt++) {
            int j0 = nt * 8 + c4 * 2;
            if (nt * 8 < len) {
                float tj0 = tv[j0], tj1 = tv[j0 + 1];
                float e00 = (j0     < len) ? __expf(acc[nt][0] - ca * fabsf(ti0 - tj0)) : 0.f;
                float e01 = (j0 + 1 < len) ? __expf(acc[nt][1] - ca * fabsf(ti0 - tj1)) : 0.f;
                float e10 = (j0     < len) ? __expf(acc[nt][2] - ca * fabsf(ti1 - tj0)) : 0.f;
                float e11 = (j0 + 1 < len) ? __expf(acc[nt][3] - ca * fabsf(ti1 - tj1)) : 0.f;
                acc[nt][0] = e00; acc[nt][1] = e01; acc[nt][2] = e10; acc[nt][3] = e11;
                s0 += e00 + e01; s1 += e10 + e11;
            }
        }
        s0 += __shfl_xor_sync(~0u, s0, 1); s0 += __shfl_xor_sync(~0u, s0, 2);
        s1 += __shfl_xor_sync(~0u, s1, 1); s1 += __shfl_xor_sync(~0u, s1, 2);
        sc0 = wv[r0] / s0;
        sc1 = wv[r1] / s1;
    }

#pragma unroll
    for (int nt = 0; nt < 16; nt++) {
        float v0 = 0.f, v1 = 0.f;
        if (wact && nt * 8 < len) {
            v0 = acc[nt][0] * sc0 + acc[nt][2] * sc1;
            v1 = acc[nt][1] * sc0 + acc[nt][3] * sc1;
        }
        v0 += __shfl_xor_sync(~0u, v0, 4);  v1 += __shfl_xor_sync(~0u, v1, 4);
        v0 += __shfl_xor_sync(~0u, v0, 8);  v1 += __shfl_xor_sync(~0u, v1, 8);
        v0 += __shfl_xor_sync(~0u, v0, 16); v1 += __shfl_xor_sync(~0u, v1, 16);
        if (g == 0) {
            int j0 = nt * 8 + c4 * 2;
            cs[w * 128 + j0] = v0;
            cs[w * 128 + j0 + 1] = v1;
        }
    }
    __syncthreads();
    if (tid < 128) {
        float p = 0.f;
#pragma unroll
        for (int q = 0; q < 8; q++) p += cs[q * 128 + tid];
        pv[tid] = p;
    }
    CP_WAIT0();
    __syncthreads();

    // ebar_d = sum_j p_j * emb_j[d]  from SMEM (Asm: d<128, Bsm: d>=128)
    const __nv_bfloat16* base = (tid < 128) ? (Asm + tid) : (Bsm + (tid - 128));
    float a = 0.f;
#pragma unroll 4
    for (int j = 0; j < len; j++)
        a = fmaf(pv[j], __bfloat162float(base[j * SA]), a);
    g_eb16[n * Dd + tid] = __float2bfloat16(a);
}

// ---- K3a: R = eb16 @ Wv -> X cols [70,326).  grid (16,2) ----
__global__ __launch_bounds__(256, 2) void k3a_R() {
    extern __shared__ __align__(16) char smraw[];
    __nv_bfloat16* Asm = (__nv_bfloat16*)smraw;
    __nv_bfloat16* Bsm = Asm + 128 * SA;
    u32 smA = (u32)__cvta_generic_to_shared(Asm);
    u32 smB = (u32)__cvta_generic_to_shared(Bsm);

    int r0 = blockIdx.x * 128, c0 = blockIdx.y * 128;
    int tid = threadIdx.x;
    int w = tid >> 5, lane = tid & 31;
    int g = lane >> 2, c4 = lane & 3;
    int warpRow = w * 16;
    u32 aAddr = smA + a_lane_off(lane, warpRow) * 2;
    u32 bAddr = smB + b_lane_off(lane) * 2;

    float acc[16][4];
#pragma unroll
    for (int t = 0; t < 16; t++)
        acc[t][0] = acc[t][1] = acc[t][2] = acc[t][3] = 0.f;

    for (int p = 0; p < 2; p++) {
        __syncthreads();
#pragma unroll
        for (int it = 0; it < 8; it++) {
            int id = tid + it * 256;
            int row = id >> 4, seg = id & 15;
            const char* gA = (const char*)(g_eb16 + (size_t)(r0 + row) * Dd + p * 128) + seg * 16;
            const char* gB = (const char*)(g_WvT16 + (size_t)(c0 + row) * Dd + p * 128) + seg * 16;
            CP_ASYNC16(smA + (row * SA + seg * 8) * 2, gA, 16);
            CP_ASYNC16(smB + (row * SA + seg * 8) * 2, gB, 16);
        }
        CP_COMMIT(); CP_WAIT0();
        __syncthreads();
        mma_ks_dense(aAddr, bAddr, acc, 0, 8);
    }
    int rr0 = r0 + warpRow + g, rr1 = rr0 + 8;
#pragma unroll
    for (int nt = 0; nt < 16; nt++) {
        int cc = DEMOd + c0 + nt * 8 + c4 * 2;
        *(u32*)(g_X16 + (size_t)rr0 * XK + cc) = pack_bf16(acc[nt][0], acc[nt][1]);
        *(u32*)(g_X16 + (size_t)rr1 * XK + cc) = pack_bf16(acc[nt][2], acc[nt][3]);
    }
}

// ---- K3b: H16 = relu(X16 @ W1 + b1).  grid (16,8), K=384 ----
__global__ __launch_bounds__(256, 2) void k3b_H(const float* __restrict__ b1) {
    extern __shared__ __align__(16) char smraw[];
    __nv_bfloat16* Asm = (__nv_bfloat16*)smraw;
    __nv_bfloat16* Bsm = Asm + 128 * SA;
    u32 smA = (u32)__cvta_generic_to_shared(Asm);
    u32 smB = (u32)__cvta_generic_to_shared(Bsm);

    int r0 = blockIdx.x * 128, c0 = blockIdx.y * 128;
    int tid = threadIdx.x;
    int w = tid >> 5, lane = tid & 31;
    int g = lane >> 2, c4 = lane & 3;
    int warpRow = w * 16;
    u32 aAddr = smA + a_lane_off(lane, warpRow) * 2;
    u32 bAddr = smB + b_lane_off(lane) * 2;

    float acc[16][4];
#pragma unroll
    for (int t = 0; t < 16; t++)
        acc[t][0] = acc[t][1] = acc[t][2] = acc[t][3] = 0.f;

    for (int p = 0; p < 3; p++) {
        __syncthreads();
#pragma unroll
        for (int it = 0; it < 8; it++) {
            int id = tid + it * 256;
            int row = id >> 4, seg = id & 15;
            const char* gA = (const char*)(g_X16 + (size_t)(r0 + row) * XK + p * 128) + seg * 16;
            const char* gB = (const char*)(g_W1T16 + (size_t)(c0 + row) * XK + p * 128) + seg * 16;
            CP_ASYNC16(smA + (row * SA + seg * 8) * 2, gA, 16);
            CP_ASYNC16(smB + (row * SA + seg * 8) * 2, gB, 16);
        }
        CP_COMMIT(); CP_WAIT0();
        __syncthreads();
        mma_ks_dense(aAddr, bAddr, acc, 0, 8);
    }
    int rr0 = r0 + warpRow + g, rr1 = rr0 + 8;
#pragma unroll
    for (int nt = 0; nt < 16; nt++) {
        int col = c0 + nt * 8 + c4 * 2;
        float b0 = b1[col], b1v = b1[col + 1];
        *(u32*)(g_H16 + (size_t)rr0 * HIDd + col) =
            pack_bf16(fmaxf(acc[nt][0] + b0, 0.f), fmaxf(acc[nt][1] + b1v, 0.f));
        *(u32*)(g_H16 + (size_t)rr1 * HIDd + col) =
            pack_bf16(fmaxf(acc[nt][2] + b0, 0.f), fmaxf(acc[nt][3] + b1v, 0.f));
    }
}

// ---- K3c: logit + weighted BCE ----
__global__ __launch_bounds__(256) void k3c_loss(const float* __restrict__ W2,
                                                const float* __restrict__ b2,
                                                const float* __restrict__ labels) {
    int warp = threadIdx.x >> 5, lane = threadIdx.x & 31;
    int n = blockIdx.x * 8 + warp;
    float s = 0.f;
    for (int q = lane; q < HIDd; q += 32)
        s = fmaf(__bfloat162float(g_H16[(size_t)n * HIDd + q]), W2[q], s);
#pragma unroll
    for (int o = 16; o; o >>= 1) s += __shfl_xor_sync(~0u, s, o);
    if (lane == 0) {
        float logit = s + b2[0];
        float y = labels[n];
        float sp = (logit > 0.f) ? logit + log1pf(expf(-logit)) : log1pf(expf(logit));
        float sp_neg = sp - logit;
        g_loss[n] = 2.0f * y * sp_neg + (1.0f - y) * sp;
    }
}

// ---- K4: deterministic reduce ----
__global__ __launch_bounds__(256) void k4_final(const float* __restrict__ c_attn,
                                                const float* __restrict__ c_pool,
                                                float* __restrict__ out) {
    __shared__ float red[256];
    int tid = threadIdx.x;
    float s = 0.f;
    for (int i = tid; i < Nn; i += 256) s += g_loss[i];
    red[tid] = s;
    __syncthreads();
    for (int st = 128; st; st >>= 1) {
        if (tid < st) red[tid] += red[tid + st];
        __syncthreads();
    }
    if (tid == 0) {
        float ca = c_attn[0], cp = c_pool[0];
        out[0] = red[0] / (float)Nn + ca * ca + cp * cp;
    }
}

static const int MMA_SMEM = 2 * 128 * SA * 2;
static const int K2_SMEM = MMA_SMEM + (8 * 128 + 3 * 128) * 4 + 128 * 4;
static const int PREP_SMEM = KC * SST64 * 4 * 2;   // 17408, covers transpose tiles too

extern "C" void kernel_launch(void* const* d_in, const int* in_sizes, int n_in,
                              void* d_out, int out_size) {
    const float* E       = (const float*)d_in[0];
    const float* Wq      = (const float*)d_in[1];
    const float* Wk      = (const float*)d_in[2];
    const float* Wv      = (const float*)d_in[3];
    const float* c_attn  = (const float*)d_in[4];
    const float* c_pool  = (const float*)d_in[5];
    const float* W1      = (const float*)d_in[6];
    const float* b1      = (const float*)d_in[7];
    const float* W2      = (const float*)d_in[8];
    const float* b2      = (const float*)d_in[9];
    const float* demo    = (const float*)d_in[10];
    const float* ht      = (const float*)d_in[11];
    const float* et      = (const float*)d_in[12];
    const float* labels  = (const float*)d_in[13];
    const int*   codes   = (const int*)d_in[14];
    const int*   lengths = (const int*)d_in[15];
    float* out = (float*)d_out;

    cudaFuncSetAttribute(k1_EM, cudaFuncAttributeMaxDynamicSharedMemorySize, MMA_SMEM);
    cudaFuncSetAttribute(k2_attn, cudaFuncAttributeMaxDynamicSharedMemorySize, K2_SMEM);
    cudaFuncSetAttribute(k3a_R, cudaFuncAttributeMaxDynamicSharedMemorySize, MMA_SMEM);
    cudaFuncSetAttribute(k3b_H, cudaFuncAttributeMaxDynamicSharedMemorySize, MMA_SMEM);

    k_prep<<<6489, 256, PREP_SMEM>>>(E, Wq, Wk, Wv, W1, demo, lengths);
    k1_EM<<<dim3(157, 2), 256, MMA_SMEM>>>();
    k2_attn<<<Nn, 256, K2_SMEM>>>(codes, ht, et, lengths, c_attn, c_pool);
    k3a_R<<<dim3(16, 2), 256, MMA_SMEM>>>();
    k3b_H<<<dim3(16, 8), 256, MMA_SMEM>>>(b1);
    k3c_loss<<<Nn / 8, 256>>>(W2, b2, labels);
    k4_final<<<1, 256>>>(c_attn, c_pool, out);
}